// round 11
// baseline (speedup 1.0000x reference)
#include <cuda_runtime.h>
#include <cuda_bf16.h>
#include <cstdint>
#include <cstddef>

#define D_MODEL 1024
#define N_HEADS 16
#define HEAD_DIM 64
#define BATCH 2
#define SEQ 2048
#define ROWS (BATCH * SEQ)   // 4096

// ---------------- scratch (__device__ globals; allocation-free rule) -------
__device__ __nv_bfloat16 g_xh[ROWS * D_MODEL];
__device__ __nv_bfloat16 g_xl[ROWS * D_MODEL];
__device__ __nv_bfloat16 g_qh[ROWS * D_MODEL];
__device__ __nv_bfloat16 g_ql[ROWS * D_MODEL];
__device__ __nv_bfloat16 g_kh[ROWS * D_MODEL];
__device__ __nv_bfloat16 g_kl[ROWS * D_MODEL];
__device__ __nv_bfloat16 g_vh[ROWS * D_MODEL];
__device__ __nv_bfloat16 g_vl[ROWS * D_MODEL];
__device__ __nv_bfloat16 g_ah[ROWS * D_MODEL];
__device__ __nv_bfloat16 g_al[ROWS * D_MODEL];
__device__ __nv_bfloat16 g_wh[4 * D_MODEL * D_MODEL];  // transposed [N,K]
__device__ __nv_bfloat16 g_wl[4 * D_MODEL * D_MODEL];

// ---------------- helpers --------------------------------------------------
__device__ __forceinline__ uint32_t smem_u32(const void* p) {
    uint32_t a;
    asm("{ .reg .u64 t; cvta.to.shared.u64 t, %1; cvt.u32.u64 %0, t; }"
        : "=r"(a) : "l"(p));
    return a;
}

__device__ __forceinline__ void cp16(uint32_t s, const void* g) {
    asm volatile("cp.async.cg.shared.global [%0], [%1], 16;" :: "r"(s), "l"(g));
}
#define CP_COMMIT() asm volatile("cp.async.commit_group;" ::: "memory")
#define CP_WAIT(n)  asm volatile("cp.async.wait_group %0;" :: "n"(n) : "memory")

__device__ __forceinline__ void ldsm_x4(uint32_t addr, uint32_t& r0, uint32_t& r1,
                                        uint32_t& r2, uint32_t& r3) {
    asm volatile("ldmatrix.sync.aligned.m8n8.x4.shared.b16 {%0,%1,%2,%3}, [%4];"
                 : "=r"(r0), "=r"(r1), "=r"(r2), "=r"(r3) : "r"(addr));
}

__device__ __forceinline__ void ldsm_x4_t(uint32_t addr, uint32_t& r0, uint32_t& r1,
                                          uint32_t& r2, uint32_t& r3) {
    asm volatile("ldmatrix.sync.aligned.m8n8.x4.trans.shared.b16 {%0,%1,%2,%3}, [%4];"
                 : "=r"(r0), "=r"(r1), "=r"(r2), "=r"(r3) : "r"(addr));
}

__device__ __forceinline__ void mma16816(float* c, const uint32_t* a, const uint32_t* b) {
    asm volatile(
        "mma.sync.aligned.m16n8k16.row.col.f32.bf16.bf16.f32 "
        "{%0,%1,%2,%3},{%4,%5,%6,%7},{%8,%9},{%0,%1,%2,%3};"
        : "+f"(c[0]), "+f"(c[1]), "+f"(c[2]), "+f"(c[3])
        : "r"(a[0]), "r"(a[1]), "r"(a[2]), "r"(a[3]), "r"(b[0]), "r"(b[1]));
}

__device__ __forceinline__ uint32_t pack_bf16(float lo, float hi) {
    uint32_t r;
    asm("cvt.rn.bf16x2.f32 %0, %1, %2;" : "=r"(r) : "f"(hi), "f"(lo));
    return r;
}

__device__ __forceinline__ float bf16_rt(float v) {
    return __bfloat162float(__float2bfloat16(v));
}

__device__ __forceinline__ float ex2(float x) {
    float r;
    asm("ex2.approx.f32 %0, %1;" : "=f"(r) : "f"(x));
    return r;
}

// ---------------------------------------------------------------------------
// Pipelined split-bf16 GEMM (cp.async double-buffer), 2 CTAs/SM forced.
// Unchanged from R9 (verified).
// ---------------------------------------------------------------------------
#define GK 1024
#define NCH (GK / 32)                // 32
#define TS 40
#define TILE_HALVES (128 * TS)       // 5120
#define TILE_BYTES (TILE_HALVES * 2) // 10240
#define STAGE_BYTES (4 * TILE_BYTES) // 40960
#define GEMM_SMEM (2 * STAGE_BYTES)  // 81920

template <int QKV>
__global__ __launch_bounds__(256, 2) void gemm_pipe(
    const __nv_bfloat16* __restrict__ Ah, const __nv_bfloat16* __restrict__ Al,
    const __nv_bfloat16* __restrict__ Bh, const __nv_bfloat16* __restrict__ Bl,
    float* __restrict__ C, __nv_bfloat16* __restrict__ H,
    __nv_bfloat16* __restrict__ L) {
    extern __shared__ __align__(16) char gsm[];
    if (QKV) {
        const size_t zo = (size_t)blockIdx.z * D_MODEL * D_MODEL;
        Ah = g_xh; Al = g_xl;
        Bh = g_wh + zo; Bl = g_wl + zo;
        H = blockIdx.z == 0 ? g_qh : blockIdx.z == 1 ? g_kh : g_vh;
        L = blockIdx.z == 0 ? g_ql : blockIdx.z == 1 ? g_kl : g_vl;
    }

    const int tid = threadIdx.x;
    const int lane = tid & 31;
    const int wid = tid >> 5;
    const int wm = wid & 3;
    const int wn = wid >> 2;
    const int mBase = wm * 32;
    const int nBase = wn * 64;
    const int bm = blockIdx.y * 128;
    const int bn = blockIdx.x * 128;
    const uint32_t sb = smem_u32(gsm);

    const int ld_r = tid >> 2, ld_c = (tid & 3) * 8;

    float c[2][8][4];
#pragma unroll
    for (int mt = 0; mt < 2; mt++)
#pragma unroll
        for (int nt = 0; nt < 8; nt++)
#pragma unroll
            for (int j = 0; j < 4; j++) c[mt][nt][j] = 0.0f;

    const int a_row = lane & 15;
    const int a_koff = (lane >> 4) * 8;
    const int b_nrow = ((lane >> 4) * 8) + (lane & 7);
    const int b_koff = ((lane >> 3) & 1) * 8;

    auto issue = [&](int ch, int stage) {
        const int k0 = ch * 32;
        const __nv_bfloat16* srcs[4] = {
            Ah + (size_t)bm * GK + k0, Al + (size_t)bm * GK + k0,
            Bh + (size_t)bn * GK + k0, Bl + (size_t)bn * GK + k0};
        const uint32_t sbase = sb + stage * STAGE_BYTES;
#pragma unroll
        for (int t = 0; t < 4; t++) {
#pragma unroll
            for (int it = 0; it < 2; it++) {
                int r = ld_r + it * 64;
                cp16(sbase + t * TILE_BYTES + (r * TS + ld_c) * 2,
                     srcs[t] + (size_t)r * GK + ld_c);
            }
        }
        CP_COMMIT();
    };

    issue(0, 0);

    for (int ch = 0; ch < NCH; ch++) {
        if (ch + 1 < NCH) {
            issue(ch + 1, (ch + 1) & 1);
            CP_WAIT(1);
        } else {
            CP_WAIT(0);
        }
        __syncthreads();
        const uint32_t base = sb + (ch & 1) * STAGE_BYTES;

#pragma unroll
        for (int ks = 0; ks < 2; ks++) {
            uint32_t aH[2][4], aL[2][4], b[8][2];
#pragma unroll
            for (int mt = 0; mt < 2; mt++) {
                uint32_t off = ((mBase + mt * 16 + a_row) * TS + ks * 16 + a_koff) * 2;
                ldsm_x4(base + off, aH[mt][0], aH[mt][1], aH[mt][2], aH[mt][3]);
                ldsm_x4(base + TILE_BYTES + off, aL[mt][0], aL[mt][1], aL[mt][2], aL[mt][3]);
            }
#pragma unroll
            for (int g = 0; g < 4; g++) {
                uint32_t off = ((nBase + g * 16 + b_nrow) * TS + ks * 16 + b_koff) * 2;
                ldsm_x4(base + 2 * TILE_BYTES + off,
                        b[2 * g][0], b[2 * g][1], b[2 * g + 1][0], b[2 * g + 1][1]);
            }
#pragma unroll
            for (int mt = 0; mt < 2; mt++)
#pragma unroll
                for (int nt = 0; nt < 8; nt++) mma16816(c[mt][nt], aH[mt], b[nt]);
#pragma unroll
            for (int mt = 0; mt < 2; mt++)
#pragma unroll
                for (int nt = 0; nt < 8; nt++) mma16816(c[mt][nt], aL[mt], b[nt]);
#pragma unroll
            for (int g = 0; g < 4; g++) {
                uint32_t off = ((nBase + g * 16 + b_nrow) * TS + ks * 16 + b_koff) * 2;
                ldsm_x4(base + 3 * TILE_BYTES + off,
                        b[2 * g][0], b[2 * g][1], b[2 * g + 1][0], b[2 * g + 1][1]);
            }
#pragma unroll
            for (int mt = 0; mt < 2; mt++)
#pragma unroll
                for (int nt = 0; nt < 8; nt++) mma16816(c[mt][nt], aH[mt], b[nt]);
        }
        __syncthreads();
    }

#pragma unroll
    for (int mt = 0; mt < 2; mt++) {
#pragma unroll
        for (int half = 0; half < 2; half++) {
            int row = bm + mBase + mt * 16 + (lane >> 2) + half * 8;
#pragma unroll
            for (int nt = 0; nt < 8; nt++) {
                int col = bn + nBase + nt * 8 + (lane & 3) * 2;
                float v0 = c[mt][nt][2 * half];
                float v1 = c[mt][nt][2 * half + 1];
                if (QKV) {
                    size_t off = (size_t)row * D_MODEL + col;
                    float h0 = bf16_rt(v0), h1 = bf16_rt(v1);
                    *(uint32_t*)(H + off) = pack_bf16(h0, h1);
                    *(uint32_t*)(L + off) = pack_bf16(v0 - h0, v1 - h1);
                } else {
                    *(float2*)(C + (size_t)row * D_MODEL + col) = make_float2(v0, v1);
                }
            }
        }
    }
}

// ---------------------------------------------------------------------------
// Conversion kernels
// ---------------------------------------------------------------------------
__global__ __launch_bounds__(256) void split_fp32(const float* __restrict__ s,
                                                  __nv_bfloat16* __restrict__ h,
                                                  __nv_bfloat16* __restrict__ l) {
    int i = blockIdx.x * 256 + threadIdx.x;
    float4 v = ((const float4*)s)[i];
    float a[4] = {v.x, v.y, v.z, v.w};
    uint32_t hh[2], ll[2];
#pragma unroll
    for (int j = 0; j < 2; j++) {
        float h0 = bf16_rt(a[2 * j]), h1 = bf16_rt(a[2 * j + 1]);
        hh[j] = pack_bf16(h0, h1);
        ll[j] = pack_bf16(a[2 * j] - h0, a[2 * j + 1] - h1);
    }
    ((uint32_t*)h)[2 * i] = hh[0];
    ((uint32_t*)h)[2 * i + 1] = hh[1];
    ((uint32_t*)l)[2 * i] = ll[0];
    ((uint32_t*)l)[2 * i + 1] = ll[1];
}

__global__ __launch_bounds__(256) void transpose_split4(const float* __restrict__ w0,
                                                        const float* __restrict__ w1,
                                                        const float* __restrict__ w2,
                                                        const float* __restrict__ w3) {
    __shared__ float t[32][33];
    const int z = blockIdx.z;
    const float* W = z == 0 ? w0 : z == 1 ? w1 : z == 2 ? w2 : w3;
    __nv_bfloat16* Th = g_wh + (size_t)z * D_MODEL * D_MODEL;
    __nv_bfloat16* Tl = g_wl + (size_t)z * D_MODEL * D_MODEL;

    int x = blockIdx.x * 32 + threadIdx.x;
    int y0 = blockIdx.y * 32;
#pragma unroll
    for (int j = 0; j < 32; j += 8)
        t[threadIdx.y + j][threadIdx.x] = W[(size_t)(y0 + threadIdx.y + j) * D_MODEL + x];
    __syncthreads();
    int xo = blockIdx.y * 32 + threadIdx.x;
    int yo = blockIdx.x * 32;
#pragma unroll
    for (int j = 0; j < 32; j += 8) {
        float v = t[threadIdx.x][threadIdx.y + j];
        float hv = bf16_rt(v);
        Th[(size_t)(yo + threadIdx.y + j) * D_MODEL + xo] = __float2bfloat16(v);
        Tl[(size_t)(yo + threadIdx.y + j) * D_MODEL + xo] = __float2bfloat16(v - hv);
    }
}

// ---------------------------------------------------------------------------
// Tensor-core causal flash attention, split-bf16, Q-in-registers.
// 64x64 tiles, 128 threads, 2-stage cp.async KV prefetch.
// Q fragments hoisted to registers (staged once through KV stage 0), so smem
// is only 2 x 36864 = 73728 B -> 3 CTAs/SM (launch_bounds(128,3), regs<=170).
// S = QhKh+QlKh+QhKl ; PV = PhVh+PlVh+PhVl. Base-2 softmax.
// ---------------------------------------------------------------------------
#define TS2 72
#define ATILE_B (64 * TS2 * 2)       // 9216 bytes per tile
#define KV_STAGE (4 * ATILE_B)       // 36864
#define ATTN_SMEM (2 * KV_STAGE)     // 73728

__global__ __launch_bounds__(128, 3) void attn_tc() {
    extern __shared__ __align__(16) char asmc[];
    const uint32_t sb = smem_u32(asmc);

    const int tid = threadIdx.x;
    const int lane = tid & 31;
    const int wq = tid >> 5;
    const int qb = gridDim.x - 1 - blockIdx.x;  // heavy blocks first
    const int bh = blockIdx.y;
    const int b = bh >> 4, h = bh & 15;

    const uint32_t a_off = ((wq * 16 + (lane & 15)) * TS2 + (lane >> 4) * 8) * 2;
    const uint32_t b_off = ((((lane >> 4) * 8) + (lane & 7)) * TS2 + ((lane >> 3) & 1) * 8) * 2;
    const uint32_t v_off = ((((lane >> 3) & 1) * 8 + (lane & 7)) * TS2 + (lane >> 4) * 8) * 2;

    // ---- stage Q through KV stage 0, hoist fragments to registers ----
    uint32_t qH[4][4], qL[4][4];
    {
        const size_t base = (size_t)(b * SEQ + qb * 64) * D_MODEL + h * 64;
#pragma unroll
        for (int it = 0; it < 4; it++) {
            int idx = tid + it * 128;
            int r = idx >> 3, c8 = (idx & 7) * 8;
            size_t g = base + (size_t)r * D_MODEL + c8;
            uint32_t so = (r * TS2 + c8) * 2;
            cp16(sb + so, g_qh + g);
            cp16(sb + ATILE_B + so, g_ql + g);
        }
        CP_COMMIT();
        CP_WAIT(0);
        __syncthreads();
#pragma unroll
        for (int ks = 0; ks < 4; ks++) {
            ldsm_x4(sb + a_off + ks * 32, qH[ks][0], qH[ks][1], qH[ks][2], qH[ks][3]);
            ldsm_x4(sb + ATILE_B + a_off + ks * 32, qL[ks][0], qL[ks][1], qL[ks][2], qL[ks][3]);
        }
        __syncthreads();  // all warps done reading Q before KV overwrites stage 0
    }

    auto issue_kv = [&](int kb, int stage) {
        const size_t base = (size_t)(b * SEQ + kb * 64) * D_MODEL + h * 64;
        const uint32_t kvb = sb + stage * KV_STAGE;
#pragma unroll
        for (int it = 0; it < 4; it++) {
            int idx = tid + it * 128;
            int r = idx >> 3, c8 = (idx & 7) * 8;
            size_t g = base + (size_t)r * D_MODEL + c8;
            uint32_t so = (r * TS2 + c8) * 2;
            cp16(kvb + so, g_kh + g);
            cp16(kvb + ATILE_B + so, g_kl + g);
            cp16(kvb + 2 * ATILE_B + so, g_vh + g);
            cp16(kvb + 3 * ATILE_B + so, g_vl + g);
        }
        CP_COMMIT();
    };

    issue_kv(0, 0);

    float O[8][4];
#pragma unroll
    for (int nt = 0; nt < 8; nt++)
#pragma unroll
        for (int j = 0; j < 4; j++) O[nt][j] = 0.0f;
    float mrow[2] = {-1e30f, -1e30f};
    float lrow[2] = {0.0f, 0.0f};

    // scale * log2(e): softmax in base-2 domain
    const float scale2 = 0.03125f * 1.44269504088896f;

    const int row0 = qb * 64 + wq * 16 + (lane >> 2);

    for (int kb = 0; kb <= qb; kb++) {
        if (kb < qb) {
            issue_kv(kb + 1, (kb + 1) & 1);
            CP_WAIT(1);
        } else {
            CP_WAIT(0);
        }
        __syncthreads();

        const uint32_t kvb = sb + (kb & 1) * KV_STAGE;
        const uint32_t SKH = kvb, SKL = kvb + ATILE_B,
                       SVH = kvb + 2 * ATILE_B, SVL = kvb + 3 * ATILE_B;

        // ---- S = Q @ K^T (split; Q from registers) ----
        float s[8][4];
#pragma unroll
        for (int nt = 0; nt < 8; nt++)
#pragma unroll
            for (int j = 0; j < 4; j++) s[nt][j] = 0.0f;

#pragma unroll
        for (int ks = 0; ks < 4; ks++) {
            uint32_t bk[8][2];
#pragma unroll
            for (int g = 0; g < 4; g++)
                ldsm_x4(SKH + b_off + g * 16 * TS2 * 2 + ks * 32,
                        bk[2 * g][0], bk[2 * g][1], bk[2 * g + 1][0], bk[2 * g + 1][1]);
#pragma unroll
            for (int nt = 0; nt < 8; nt++) mma16816(s[nt], qH[ks], bk[nt]);
#pragma unroll
            for (int nt = 0; nt < 8; nt++) mma16816(s[nt], qL[ks], bk[nt]);
#pragma unroll
            for (int g = 0; g < 4; g++)
                ldsm_x4(SKL + b_off + g * 16 * TS2 * 2 + ks * 32,
                        bk[2 * g][0], bk[2 * g][1], bk[2 * g + 1][0], bk[2 * g + 1][1]);
#pragma unroll
            for (int nt = 0; nt < 8; nt++) mma16816(s[nt], qH[ks], bk[nt]);
        }

        // ---- scale + mask + online softmax (base-2) ----
        const bool diag = (kb == qb);
#pragma unroll
        for (int i = 0; i < 2; i++) {
            const int rg = row0 + i * 8;
            float mx = -1e30f;
#pragma unroll
            for (int nt = 0; nt < 8; nt++) {
#pragma unroll
                for (int j = 0; j < 2; j++) {
                    float v = s[nt][2 * i + j] * scale2;
                    if (diag) {
                        int cg = kb * 64 + nt * 8 + (lane & 3) * 2 + j;
                        if (cg > rg) v = -1e30f;
                    }
                    s[nt][2 * i + j] = v;
                    mx = fmaxf(mx, v);
                }
            }
            mx = fmaxf(mx, __shfl_xor_sync(0xffffffffu, mx, 1));
            mx = fmaxf(mx, __shfl_xor_sync(0xffffffffu, mx, 2));
            float mn = fmaxf(mrow[i], mx);
            float alpha = ex2(mrow[i] - mn);
            mrow[i] = mn;
            float rs = 0.0f;
#pragma unroll
            for (int nt = 0; nt < 8; nt++) {
#pragma unroll
                for (int j = 0; j < 2; j++) {
                    float p = ex2(s[nt][2 * i + j] - mn);
                    s[nt][2 * i + j] = p;
                    rs += p;
                }
            }
            rs += __shfl_xor_sync(0xffffffffu, rs, 1);
            rs += __shfl_xor_sync(0xffffffffu, rs, 2);
            lrow[i] = lrow[i] * alpha + rs;
#pragma unroll
            for (int nt = 0; nt < 8; nt++) {
                O[nt][2 * i] *= alpha;
                O[nt][2 * i + 1] *= alpha;
            }
        }

        // ---- O += P @ V (split; P from registers) ----
#pragma unroll
        for (int g = 0; g < 4; g++) {
            uint32_t pH[4], pL[4];
#pragma unroll
            for (int q2 = 0; q2 < 2; q2++) {
#pragma unroll
                for (int half = 0; half < 2; half++) {
                    float v0 = s[2 * g + q2][2 * half];
                    float v1 = s[2 * g + q2][2 * half + 1];
                    float h0 = bf16_rt(v0), h1 = bf16_rt(v1);
                    pH[2 * q2 + half] = pack_bf16(h0, h1);
                    pL[2 * q2 + half] = pack_bf16(v0 - h0, v1 - h1);
                }
            }
            uint32_t bv[8][2];
#pragma unroll
            for (int gn = 0; gn < 4; gn++)
                ldsm_x4_t(SVH + v_off + (g * 16 * TS2 + gn * 16) * 2,
                          bv[2 * gn][0], bv[2 * gn][1], bv[2 * gn + 1][0], bv[2 * gn + 1][1]);
#pragma unroll
            for (int nt = 0; nt < 8; nt++) mma16816(O[nt], pH, bv[nt]);
#pragma unroll
            for (int nt = 0; nt < 8; nt++) mma16816(O[nt], pL, bv[nt]);
#pragma unroll
            for (int gn = 0; gn < 4; gn++)
                ldsm_x4_t(SVL + v_off + (g * 16 * TS2 + gn * 16) * 2,
                          bv[2 * gn][0], bv[2 * gn][1], bv[2 * gn + 1][0], bv[2 * gn + 1][1]);
#pragma unroll
            for (int nt = 0; nt < 8; nt++) mma16816(O[nt], pH, bv[nt]);
        }
        __syncthreads();
    }

    // ---- epilogue ----
#pragma unroll
    for (int i = 0; i < 2; i++) {
        float inv = 1.0f / lrow[i];
        size_t row = (size_t)(b * SEQ) + row0 + i * 8;
#pragma unroll
        for (int nt = 0; nt < 8; nt++) {
            size_t off = row * D_MODEL + h * 64 + nt * 8 + (lane & 3) * 2;
            float v0 = O[nt][2 * i] * inv;
            float v1 = O[nt][2 * i + 1] * inv;
            float h0 = bf16_rt(v0), h1 = bf16_rt(v1);
            *(uint32_t*)(g_ah + off) = pack_bf16(h0, h1);
            *(uint32_t*)(g_al + off) = pack_bf16(v0 - h0, v1 - h1);
        }
    }
}

// ---------------------------------------------------------------------------
// kernel_launch: x, qw, kw, vw, ow (fp32)
// ---------------------------------------------------------------------------
extern "C" void kernel_launch(void* const* d_in, const int* in_sizes, int n_in,
                              void* d_out, int out_size) {
    const float* x = (const float*)d_in[0];
    float* out = (float*)d_out;

    __nv_bfloat16 *xh, *xl, *ah, *al, *wh, *wl;
    cudaGetSymbolAddress((void**)&xh, g_xh);
    cudaGetSymbolAddress((void**)&xl, g_xl);
    cudaGetSymbolAddress((void**)&ah, g_ah);
    cudaGetSymbolAddress((void**)&al, g_al);
    cudaGetSymbolAddress((void**)&wh, g_wh);
    cudaGetSymbolAddress((void**)&wl, g_wl);

    cudaFuncSetAttribute(gemm_pipe<1>, cudaFuncAttributeMaxDynamicSharedMemorySize,
                         GEMM_SMEM);
    cudaFuncSetAttribute(gemm_pipe<0>, cudaFuncAttributeMaxDynamicSharedMemorySize,
                         GEMM_SMEM);
    cudaFuncSetAttribute(attn_tc, cudaFuncAttributeMaxDynamicSharedMemorySize,
                         ATTN_SMEM);

    // 1. split x into bf16 hi/lo
    split_fp32<<<(ROWS * D_MODEL / 4) / 256, 256>>>(x, xh, xl);
    // 2. transpose+split all 4 weights (one launch)
    transpose_split4<<<dim3(32, 32, 4), dim3(32, 8)>>>(
        (const float*)d_in[1], (const float*)d_in[2],
        (const float*)d_in[3], (const float*)d_in[4]);

    // 3. fused Q/K/V projections (pipelined, 2 CTAs/SM)
    gemm_pipe<1><<<dim3(D_MODEL / 128, ROWS / 128, 3), 256, GEMM_SMEM>>>(
        nullptr, nullptr, nullptr, nullptr, nullptr, nullptr, nullptr);

    // 4. tensor-core attention (Q in registers, 3 CTAs/SM)
    attn_tc<<<dim3(SEQ / 64, BATCH * N_HEADS), 128, ATTN_SMEM>>>();

    // 5. output projection (fp32 epilogue to d_out)
    gemm_pipe<0><<<dim3(D_MODEL / 128, ROWS / 128, 1), 256, GEMM_SMEM>>>(
        ah, al, wh + 3u * D_MODEL * D_MODEL, wl + 3u * D_MODEL * D_MODEL,
        out, nullptr, nullptr);
}

// round 13
// speedup vs baseline: 1.1826x; 1.1826x over previous
#include <cuda_runtime.h>
#include <cuda_fp16.h>
#include <cstdint>
#include <cstddef>

#define D_MODEL 1024
#define N_HEADS 16
#define HEAD_DIM 64
#define BATCH 2
#define SEQ 2048
#define ROWS (BATCH * SEQ)   // 4096

// ---------------- scratch (__device__ globals; allocation-free rule) -------
__device__ __half g_xh[ROWS * D_MODEL];
__device__ __half g_xl[ROWS * D_MODEL];
__device__ __half g_qh[ROWS * D_MODEL];
__device__ __half g_ql[ROWS * D_MODEL];
__device__ __half g_kh[ROWS * D_MODEL];
__device__ __half g_kl[ROWS * D_MODEL];
__device__ __half g_vh[ROWS * D_MODEL];
__device__ __half g_ah[ROWS * D_MODEL];
__device__ __half g_al[ROWS * D_MODEL];
__device__ __half g_wh[4 * D_MODEL * D_MODEL];  // transposed [N,K]
__device__ __half g_wl[4 * D_MODEL * D_MODEL];  // lo only used by Q/K proj

// ---------------- helpers --------------------------------------------------
__device__ __forceinline__ uint32_t smem_u32(const void* p) {
    uint32_t a;
    asm("{ .reg .u64 t; cvta.to.shared.u64 t, %1; cvt.u32.u64 %0, t; }"
        : "=r"(a) : "l"(p));
    return a;
}

__device__ __forceinline__ void cp16(uint32_t s, const void* g) {
    asm volatile("cp.async.cg.shared.global [%0], [%1], 16;" :: "r"(s), "l"(g));
}
#define CP_COMMIT() asm volatile("cp.async.commit_group;" ::: "memory")
#define CP_WAIT(n)  asm volatile("cp.async.wait_group %0;" :: "n"(n) : "memory")

__device__ __forceinline__ void ldsm_x4(uint32_t addr, uint32_t& r0, uint32_t& r1,
                                        uint32_t& r2, uint32_t& r3) {
    asm volatile("ldmatrix.sync.aligned.m8n8.x4.shared.b16 {%0,%1,%2,%3}, [%4];"
                 : "=r"(r0), "=r"(r1), "=r"(r2), "=r"(r3) : "r"(addr));
}

__device__ __forceinline__ void ldsm_x4_t(uint32_t addr, uint32_t& r0, uint32_t& r1,
                                          uint32_t& r2, uint32_t& r3) {
    asm volatile("ldmatrix.sync.aligned.m8n8.x4.trans.shared.b16 {%0,%1,%2,%3}, [%4];"
                 : "=r"(r0), "=r"(r1), "=r"(r2), "=r"(r3) : "r"(addr));
}

__device__ __forceinline__ void mma16816(float* c, const uint32_t* a, const uint32_t* b) {
    asm volatile(
        "mma.sync.aligned.m16n8k16.row.col.f32.f16.f16.f32 "
        "{%0,%1,%2,%3},{%4,%5,%6,%7},{%8,%9},{%0,%1,%2,%3};"
        : "+f"(c[0]), "+f"(c[1]), "+f"(c[2]), "+f"(c[3])
        : "r"(a[0]), "r"(a[1]), "r"(a[2]), "r"(a[3]), "r"(b[0]), "r"(b[1]));
}

__device__ __forceinline__ uint32_t pack_f16(float lo, float hi) {
    uint32_t r;
    asm("cvt.rn.f16x2.f32 %0, %1, %2;" : "=r"(r) : "f"(hi), "f"(lo));
    return r;
}

__device__ __forceinline__ float f16_rt(float v) {
    return __half2float(__float2half_rn(v));
}

__device__ __forceinline__ float ex2(float x) {
    float r;
    asm("ex2.approx.f32 %0, %1;" : "=f"(r) : "f"(x));
    return r;
}

// ---------------------------------------------------------------------------
// Pipelined split-fp16 GEMM (cp.async double-buffer), 2 CTAs/SM.
// C[M,N] = (Ah+Al)[M,K] @ (Bh+Bl)^T, B transposed [N,K]. CTA tile 128x128,
// BK=32, 256 threads, warp tile m32 x n64.
// nprod=3: AhBh + AlBh + AhBl (Q/K proj). nprod=2: AhBh + AlBh (V/out proj,
// Bl never loaded).
// QKV=1: grid.z selects weight/output from device globals, split epilogue.
// QKV=0: fp32 epilogue to C, 2 products.
// ---------------------------------------------------------------------------
#define GK 1024
#define NCH (GK / 32)                // 32
#define TS 40
#define TILE_HALVES (128 * TS)       // 5120
#define TILE_BYTES (TILE_HALVES * 2) // 10240
#define STAGE_BYTES (4 * TILE_BYTES) // 40960
#define GEMM_SMEM (2 * STAGE_BYTES)  // 81920

template <int QKV>
__global__ __launch_bounds__(256, 2) void gemm_pipe(
    const __half* __restrict__ Ah, const __half* __restrict__ Al,
    const __half* __restrict__ Bh, const __half* __restrict__ Bl,
    float* __restrict__ C, __half* __restrict__ H, __half* __restrict__ L) {
    extern __shared__ __align__(16) char gsm[];
    int nprod = 2;
    bool storeL = true;
    if (QKV) {
        const size_t zo = (size_t)blockIdx.z * D_MODEL * D_MODEL;
        Ah = g_xh; Al = g_xl;
        Bh = g_wh + zo; Bl = g_wl + zo;
        if (blockIdx.z == 0) { H = g_qh; L = g_ql; nprod = 3; }
        else if (blockIdx.z == 1) { H = g_kh; L = g_kl; nprod = 3; }
        else { H = g_vh; L = nullptr; storeL = false; }   // V: 2 products, hi only
    }

    const int tid = threadIdx.x;
    const int lane = tid & 31;
    const int wid = tid >> 5;
    const int wm = wid & 3;
    const int wn = wid >> 2;
    const int mBase = wm * 32;
    const int nBase = wn * 64;
    const int bm = blockIdx.y * 128;
    const int bn = blockIdx.x * 128;
    const uint32_t sb = smem_u32(gsm);

    const int ld_r = tid >> 2, ld_c = (tid & 3) * 8;

    float c[2][8][4];
#pragma unroll
    for (int mt = 0; mt < 2; mt++)
#pragma unroll
        for (int nt = 0; nt < 8; nt++)
#pragma unroll
            for (int j = 0; j < 4; j++) c[mt][nt][j] = 0.0f;

    const int a_row = lane & 15;
    const int a_koff = (lane >> 4) * 8;
    const int b_nrow = ((lane >> 4) * 8) + (lane & 7);
    const int b_koff = ((lane >> 3) & 1) * 8;

    auto issue = [&](int ch, int stage) {
        const int k0 = ch * 32;
        const __half* srcs[4] = {
            Ah + (size_t)bm * GK + k0, Al + (size_t)bm * GK + k0,
            Bh + (size_t)bn * GK + k0, Bl ? Bl + (size_t)bn * GK + k0 : nullptr};
        const uint32_t sbase = sb + stage * STAGE_BYTES;
        const int ntiles = (nprod == 3) ? 4 : 3;
        for (int t = 0; t < ntiles; t++) {
#pragma unroll
            for (int it = 0; it < 2; it++) {
                int r = ld_r + it * 64;
                cp16(sbase + t * TILE_BYTES + (r * TS + ld_c) * 2,
                     srcs[t] + (size_t)r * GK + ld_c);
            }
        }
        CP_COMMIT();
    };

    issue(0, 0);

    for (int ch = 0; ch < NCH; ch++) {
        if (ch + 1 < NCH) {
            issue(ch + 1, (ch + 1) & 1);
            CP_WAIT(1);
        } else {
            CP_WAIT(0);
        }
        __syncthreads();
        const uint32_t base = sb + (ch & 1) * STAGE_BYTES;

#pragma unroll
        for (int ks = 0; ks < 2; ks++) {
            uint32_t aH[2][4], aL[2][4], b[8][2];
#pragma unroll
            for (int mt = 0; mt < 2; mt++) {
                uint32_t off = ((mBase + mt * 16 + a_row) * TS + ks * 16 + a_koff) * 2;
                ldsm_x4(base + off, aH[mt][0], aH[mt][1], aH[mt][2], aH[mt][3]);
                ldsm_x4(base + TILE_BYTES + off, aL[mt][0], aL[mt][1], aL[mt][2], aL[mt][3]);
            }
#pragma unroll
            for (int g = 0; g < 4; g++) {
                uint32_t off = ((nBase + g * 16 + b_nrow) * TS + ks * 16 + b_koff) * 2;
                ldsm_x4(base + 2 * TILE_BYTES + off,
                        b[2 * g][0], b[2 * g][1], b[2 * g + 1][0], b[2 * g + 1][1]);
            }
#pragma unroll
            for (int mt = 0; mt < 2; mt++)
#pragma unroll
                for (int nt = 0; nt < 8; nt++) mma16816(c[mt][nt], aH[mt], b[nt]);
#pragma unroll
            for (int mt = 0; mt < 2; mt++)
#pragma unroll
                for (int nt = 0; nt < 8; nt++) mma16816(c[mt][nt], aL[mt], b[nt]);
            if (nprod == 3) {
#pragma unroll
                for (int g = 0; g < 4; g++) {
                    uint32_t off = ((nBase + g * 16 + b_nrow) * TS + ks * 16 + b_koff) * 2;
                    ldsm_x4(base + 3 * TILE_BYTES + off,
                            b[2 * g][0], b[2 * g][1], b[2 * g + 1][0], b[2 * g + 1][1]);
                }
#pragma unroll
                for (int mt = 0; mt < 2; mt++)
#pragma unroll
                    for (int nt = 0; nt < 8; nt++) mma16816(c[mt][nt], aH[mt], b[nt]);
            }
        }
        __syncthreads();
    }

#pragma unroll
    for (int mt = 0; mt < 2; mt++) {
#pragma unroll
        for (int half = 0; half < 2; half++) {
            int row = bm + mBase + mt * 16 + (lane >> 2) + half * 8;
#pragma unroll
            for (int nt = 0; nt < 8; nt++) {
                int col = bn + nBase + nt * 8 + (lane & 3) * 2;
                float v0 = c[mt][nt][2 * half];
                float v1 = c[mt][nt][2 * half + 1];
                if (QKV) {
                    size_t off = (size_t)row * D_MODEL + col;
                    float h0 = f16_rt(v0), h1 = f16_rt(v1);
                    *(uint32_t*)(H + off) = pack_f16(h0, h1);
                    if (storeL)
                        *(uint32_t*)(L + off) = pack_f16(v0 - h0, v1 - h1);
                } else {
                    *(float2*)(C + (size_t)row * D_MODEL + col) = make_float2(v0, v1);
                }
            }
        }
    }
}

// ---------------------------------------------------------------------------
// Conversion kernels
// ---------------------------------------------------------------------------
__global__ __launch_bounds__(256) void split_fp32(const float* __restrict__ s,
                                                  __half* __restrict__ h,
                                                  __half* __restrict__ l) {
    int i = blockIdx.x * 256 + threadIdx.x;
    float4 v = ((const float4*)s)[i];
    float a[4] = {v.x, v.y, v.z, v.w};
    uint32_t hh[2], ll[2];
#pragma unroll
    for (int j = 0; j < 2; j++) {
        float h0 = f16_rt(a[2 * j]), h1 = f16_rt(a[2 * j + 1]);
        hh[j] = pack_f16(h0, h1);
        ll[j] = pack_f16(a[2 * j] - h0, a[2 * j + 1] - h1);
    }
    ((uint32_t*)h)[2 * i] = hh[0];
    ((uint32_t*)h)[2 * i + 1] = hh[1];
    ((uint32_t*)l)[2 * i] = ll[0];
    ((uint32_t*)l)[2 * i + 1] = ll[1];
}

__global__ __launch_bounds__(256) void transpose_split4(const float* __restrict__ w0,
                                                        const float* __restrict__ w1,
                                                        const float* __restrict__ w2,
                                                        const float* __restrict__ w3) {
    __shared__ float t[32][33];
    const int z = blockIdx.z;
    const float* W = z == 0 ? w0 : z == 1 ? w1 : z == 2 ? w2 : w3;
    __half* Th = g_wh + (size_t)z * D_MODEL * D_MODEL;
    __half* Tl = g_wl + (size_t)z * D_MODEL * D_MODEL;

    int x = blockIdx.x * 32 + threadIdx.x;
    int y0 = blockIdx.y * 32;
#pragma unroll
    for (int j = 0; j < 32; j += 8)
        t[threadIdx.y + j][threadIdx.x] = W[(size_t)(y0 + threadIdx.y + j) * D_MODEL + x];
    __syncthreads();
    int xo = blockIdx.y * 32 + threadIdx.x;
    int yo = blockIdx.x * 32;
#pragma unroll
    for (int j = 0; j < 32; j += 8) {
        float v = t[threadIdx.x][threadIdx.y + j];
        float hv = f16_rt(v);
        Th[(size_t)(yo + threadIdx.y + j) * D_MODEL + xo] = __float2half_rn(v);
        Tl[(size_t)(yo + threadIdx.y + j) * D_MODEL + xo] = __float2half_rn(v - hv);
    }
}

// ---------------------------------------------------------------------------
// Tensor-core causal flash attention, split-fp16, Q-in-registers.
// 64x64 tiles, 128 threads, 2-stage cp.async KV prefetch (3 tiles/stage:
// Kh, Kl, Vh — no Vl). S = QhKh+QlKh+QhKl (3 prod); PV = PhVh+PlVh (2 prod).
// Smem 2 x 27648 = 55296 B. Base-2 softmax.
// ---------------------------------------------------------------------------
#define TS2 72
#define ATILE_B (64 * TS2 * 2)       // 9216 bytes per tile
#define KV_STAGE (3 * ATILE_B)       // 27648
#define ATTN_SMEM (2 * KV_STAGE)     // 55296

__global__ __launch_bounds__(128, 3) void attn_tc() {
    extern __shared__ __align__(16) char asmc[];
    const uint32_t sb = smem_u32(asmc);

    const int tid = threadIdx.x;
    const int lane = tid & 31;
    const int wq = tid >> 5;
    const int qb = gridDim.x - 1 - blockIdx.x;  // heavy blocks first
    const int bh = blockIdx.y;
    const int b = bh >> 4, h = bh & 15;

    const uint32_t a_off = ((wq * 16 + (lane & 15)) * TS2 + (lane >> 4) * 8) * 2;
    const uint32_t b_off = ((((lane >> 4) * 8) + (lane & 7)) * TS2 + ((lane >> 3) & 1) * 8) * 2;
    const uint32_t v_off = ((((lane >> 3) & 1) * 8 + (lane & 7)) * TS2 + (lane >> 4) * 8) * 2;

    // ---- stage Q through KV stage 0, hoist fragments to registers ----
    uint32_t qH[4][4], qL[4][4];
    {
        const size_t base = (size_t)(b * SEQ + qb * 64) * D_MODEL + h * 64;
#pragma unroll
        for (int it = 0; it < 4; it++) {
            int idx = tid + it * 128;
            int r = idx >> 3, c8 = (idx & 7) * 8;
            size_t g = base + (size_t)r * D_MODEL + c8;
            uint32_t so = (r * TS2 + c8) * 2;
            cp16(sb + so, g_qh + g);
            cp16(sb + ATILE_B + so, g_ql + g);
        }
        CP_COMMIT();
        CP_WAIT(0);
        __syncthreads();
#pragma unroll
        for (int ks = 0; ks < 4; ks++) {
            ldsm_x4(sb + a_off + ks * 32, qH[ks][0], qH[ks][1], qH[ks][2], qH[ks][3]);
            ldsm_x4(sb + ATILE_B + a_off + ks * 32, qL[ks][0], qL[ks][1], qL[ks][2], qL[ks][3]);
        }
        __syncthreads();  // all warps done reading Q before KV overwrites stage 0
    }

    auto issue_kv = [&](int kb, int stage) {
        const size_t base = (size_t)(b * SEQ + kb * 64) * D_MODEL + h * 64;
        const uint32_t kvb = sb + stage * KV_STAGE;
#pragma unroll
        for (int it = 0; it < 4; it++) {
            int idx = tid + it * 128;
            int r = idx >> 3, c8 = (idx & 7) * 8;
            size_t g = base + (size_t)r * D_MODEL + c8;
            uint32_t so = (r * TS2 + c8) * 2;
            cp16(kvb + so, g_kh + g);
            cp16(kvb + ATILE_B + so, g_kl + g);
            cp16(kvb + 2 * ATILE_B + so, g_vh + g);
        }
        CP_COMMIT();
    };

    issue_kv(0, 0);

    float O[8][4];
#pragma unroll
    for (int nt = 0; nt < 8; nt++)
#pragma unroll
        for (int j = 0; j < 4; j++) O[nt][j] = 0.0f;
    float mrow[2] = {-1e30f, -1e30f};
    float lrow[2] = {0.0f, 0.0f};

    // scale * log2(e): softmax in base-2 domain
    const float scale2 = 0.03125f * 1.44269504088896f;

    const int row0 = qb * 64 + wq * 16 + (lane >> 2);

    for (int kb = 0; kb <= qb; kb++) {
        if (kb < qb) {
            issue_kv(kb + 1, (kb + 1) & 1);
            CP_WAIT(1);
        } else {
            CP_WAIT(0);
        }
        __syncthreads();

        const uint32_t kvb = sb + (kb & 1) * KV_STAGE;
        const uint32_t SKH = kvb, SKL = kvb + ATILE_B, SVH = kvb + 2 * ATILE_B;

        // ---- S = Q @ K^T (3 products; Q from registers) ----
        float s[8][4];
#pragma unroll
        for (int nt = 0; nt < 8; nt++)
#pragma unroll
            for (int j = 0; j < 4; j++) s[nt][j] = 0.0f;

#pragma unroll
        for (int ks = 0; ks < 4; ks++) {
            uint32_t bk[8][2];
#pragma unroll
            for (int g = 0; g < 4; g++)
                ldsm_x4(SKH + b_off + g * 16 * TS2 * 2 + ks * 32,
                        bk[2 * g][0], bk[2 * g][1], bk[2 * g + 1][0], bk[2 * g + 1][1]);
#pragma unroll
            for (int nt = 0; nt < 8; nt++) mma16816(s[nt], qH[ks], bk[nt]);
#pragma unroll
            for (int nt = 0; nt < 8; nt++) mma16816(s[nt], qL[ks], bk[nt]);
#pragma unroll
            for (int g = 0; g < 4; g++)
                ldsm_x4(SKL + b_off + g * 16 * TS2 * 2 + ks * 32,
                        bk[2 * g][0], bk[2 * g][1], bk[2 * g + 1][0], bk[2 * g + 1][1]);
#pragma unroll
            for (int nt = 0; nt < 8; nt++) mma16816(s[nt], qH[ks], bk[nt]);
        }

        // ---- scale + mask + online softmax (base-2) ----
        const bool diag = (kb == qb);
#pragma unroll
        for (int i = 0; i < 2; i++) {
            const int rg = row0 + i * 8;
            float mx = -1e30f;
#pragma unroll
            for (int nt = 0; nt < 8; nt++) {
#pragma unroll
                for (int j = 0; j < 2; j++) {
                    float v = s[nt][2 * i + j] * scale2;
                    if (diag) {
                        int cg = kb * 64 + nt * 8 + (lane & 3) * 2 + j;
                        if (cg > rg) v = -1e30f;
                    }
                    s[nt][2 * i + j] = v;
                    mx = fmaxf(mx, v);
                }
            }
            mx = fmaxf(mx, __shfl_xor_sync(0xffffffffu, mx, 1));
            mx = fmaxf(mx, __shfl_xor_sync(0xffffffffu, mx, 2));
            float mn = fmaxf(mrow[i], mx);
            float alpha = ex2(mrow[i] - mn);
            mrow[i] = mn;
            float rs = 0.0f;
#pragma unroll
            for (int nt = 0; nt < 8; nt++) {
#pragma unroll
                for (int j = 0; j < 2; j++) {
                    float p = ex2(s[nt][2 * i + j] - mn);
                    s[nt][2 * i + j] = p;
                    rs += p;
                }
            }
            rs += __shfl_xor_sync(0xffffffffu, rs, 1);
            rs += __shfl_xor_sync(0xffffffffu, rs, 2);
            lrow[i] = lrow[i] * alpha + rs;
#pragma unroll
            for (int nt = 0; nt < 8; nt++) {
                O[nt][2 * i] *= alpha;
                O[nt][2 * i + 1] *= alpha;
            }
        }

        // ---- O += P @ V (2 products: PhVh + PlVh) ----
#pragma unroll
        for (int g = 0; g < 4; g++) {
            uint32_t pH[4], pL[4];
#pragma unroll
            for (int q2 = 0; q2 < 2; q2++) {
#pragma unroll
                for (int half = 0; half < 2; half++) {
                    float v0 = s[2 * g + q2][2 * half];
                    float v1 = s[2 * g + q2][2 * half + 1];
                    float h0 = f16_rt(v0), h1 = f16_rt(v1);
                    pH[2 * q2 + half] = pack_f16(h0, h1);
                    pL[2 * q2 + half] = pack_f16(v0 - h0, v1 - h1);
                }
            }
            uint32_t bv[8][2];
#pragma unroll
            for (int gn = 0; gn < 4; gn++)
                ldsm_x4_t(SVH + v_off + (g * 16 * TS2 + gn * 16) * 2,
                          bv[2 * gn][0], bv[2 * gn][1], bv[2 * gn + 1][0], bv[2 * gn + 1][1]);
#pragma unroll
            for (int nt = 0; nt < 8; nt++) mma16816(O[nt], pH, bv[nt]);
#pragma unroll
            for (int nt = 0; nt < 8; nt++) mma16816(O[nt], pL, bv[nt]);
        }
        __syncthreads();
    }

    // ---- epilogue ----
#pragma unroll
    for (int i = 0; i < 2; i++) {
        float inv = 1.0f / lrow[i];
        size_t row = (size_t)(b * SEQ) + row0 + i * 8;
#pragma unroll
        for (int nt = 0; nt < 8; nt++) {
            size_t off = row * D_MODEL + h * 64 + nt * 8 + (lane & 3) * 2;
            float v0 = O[nt][2 * i] * inv;
            float v1 = O[nt][2 * i + 1] * inv;
            float h0 = f16_rt(v0), h1 = f16_rt(v1);
            *(uint32_t*)(g_ah + off) = pack_f16(h0, h1);
            *(uint32_t*)(g_al + off) = pack_f16(v0 - h0, v1 - h1);
        }
    }
}

// ---------------------------------------------------------------------------
// kernel_launch: x, qw, kw, vw, ow (fp32)
// ---------------------------------------------------------------------------
extern "C" void kernel_launch(void* const* d_in, const int* in_sizes, int n_in,
                              void* d_out, int out_size) {
    const float* x = (const float*)d_in[0];
    float* out = (float*)d_out;

    __half *xh, *xl, *ah, *al, *wh, *wl;
    cudaGetSymbolAddress((void**)&xh, g_xh);
    cudaGetSymbolAddress((void**)&xl, g_xl);
    cudaGetSymbolAddress((void**)&ah, g_ah);
    cudaGetSymbolAddress((void**)&al, g_al);
    cudaGetSymbolAddress((void**)&wh, g_wh);
    cudaGetSymbolAddress((void**)&wl, g_wl);

    cudaFuncSetAttribute(gemm_pipe<1>, cudaFuncAttributeMaxDynamicSharedMemorySize,
                         GEMM_SMEM);
    cudaFuncSetAttribute(gemm_pipe<0>, cudaFuncAttributeMaxDynamicSharedMemorySize,
                         GEMM_SMEM);
    cudaFuncSetAttribute(attn_tc, cudaFuncAttributeMaxDynamicSharedMemorySize,
                         ATTN_SMEM);

    // 1. split x into fp16 hi/lo
    split_fp32<<<(ROWS * D_MODEL / 4) / 256, 256>>>(x, xh, xl);
    // 2. transpose+split all 4 weights (one launch)
    transpose_split4<<<dim3(32, 32, 4), dim3(32, 8)>>>(
        (const float*)d_in[1], (const float*)d_in[2],
        (const float*)d_in[3], (const float*)d_in[4]);

    // 3. fused Q/K/V projections (Q,K 3-product; V 2-product)
    gemm_pipe<1><<<dim3(D_MODEL / 128, ROWS / 128, 3), 256, GEMM_SMEM>>>(
        nullptr, nullptr, nullptr, nullptr, nullptr, nullptr, nullptr);

    // 4. tensor-core attention (Q in regs; PV 2-product; no Vl)
    attn_tc<<<dim3(SEQ / 64, BATCH * N_HEADS), 128, ATTN_SMEM>>>();

    // 5. output projection (2-product, fp32 epilogue to d_out)
    gemm_pipe<0><<<dim3(D_MODEL / 128, ROWS / 128, 1), 256, GEMM_SMEM>>>(
        ah, al, wh + 3u * D_MODEL * D_MODEL, nullptr, out, nullptr, nullptr);
}

// round 15
// speedup vs baseline: 1.2165x; 1.0286x over previous
#include <cuda_runtime.h>
#include <cuda_fp16.h>
#include <cstdint>
#include <cstddef>

#define D_MODEL 1024
#define N_HEADS 16
#define HEAD_DIM 64
#define BATCH 2
#define SEQ 2048
#define ROWS (BATCH * SEQ)   // 4096

// ---------------- scratch (__device__ globals; allocation-free rule) -------
__device__ __half g_xh[ROWS * D_MODEL];
__device__ __half g_xl[ROWS * D_MODEL];
__device__ __half g_qh[ROWS * D_MODEL];
__device__ __half g_ql[ROWS * D_MODEL];
__device__ __half g_kh[ROWS * D_MODEL];
__device__ __half g_kl[ROWS * D_MODEL];
__device__ __half g_vh[ROWS * D_MODEL];
__device__ __half g_ah[ROWS * D_MODEL];
__device__ __half g_al[ROWS * D_MODEL];
__device__ __half g_wh[4 * D_MODEL * D_MODEL];  // transposed [N,K]
__device__ __half g_wl[4 * D_MODEL * D_MODEL];  // lo only used by Q/K proj

// ---------------- helpers --------------------------------------------------
__device__ __forceinline__ uint32_t smem_u32(const void* p) {
    uint32_t a;
    asm("{ .reg .u64 t; cvta.to.shared.u64 t, %1; cvt.u32.u64 %0, t; }"
        : "=r"(a) : "l"(p));
    return a;
}

__device__ __forceinline__ void cp16(uint32_t s, const void* g) {
    asm volatile("cp.async.cg.shared.global [%0], [%1], 16;" :: "r"(s), "l"(g));
}
#define CP_COMMIT() asm volatile("cp.async.commit_group;" ::: "memory")
#define CP_WAIT(n)  asm volatile("cp.async.wait_group %0;" :: "n"(n) : "memory")

__device__ __forceinline__ void ldsm_x4(uint32_t addr, uint32_t& r0, uint32_t& r1,
                                        uint32_t& r2, uint32_t& r3) {
    asm volatile("ldmatrix.sync.aligned.m8n8.x4.shared.b16 {%0,%1,%2,%3}, [%4];"
                 : "=r"(r0), "=r"(r1), "=r"(r2), "=r"(r3) : "r"(addr));
}

__device__ __forceinline__ void ldsm_x4_t(uint32_t addr, uint32_t& r0, uint32_t& r1,
                                          uint32_t& r2, uint32_t& r3) {
    asm volatile("ldmatrix.sync.aligned.m8n8.x4.trans.shared.b16 {%0,%1,%2,%3}, [%4];"
                 : "=r"(r0), "=r"(r1), "=r"(r2), "=r"(r3) : "r"(addr));
}

__device__ __forceinline__ void mma16816(float* c, const uint32_t* a, const uint32_t* b) {
    asm volatile(
        "mma.sync.aligned.m16n8k16.row.col.f32.f16.f16.f32 "
        "{%0,%1,%2,%3},{%4,%5,%6,%7},{%8,%9},{%0,%1,%2,%3};"
        : "+f"(c[0]), "+f"(c[1]), "+f"(c[2]), "+f"(c[3])
        : "r"(a[0]), "r"(a[1]), "r"(a[2]), "r"(a[3]), "r"(b[0]), "r"(b[1]));
}

__device__ __forceinline__ uint32_t pack_f16(float lo, float hi) {
    uint32_t r;
    asm("cvt.rn.f16x2.f32 %0, %1, %2;" : "=r"(r) : "f"(hi), "f"(lo));
    return r;
}

__device__ __forceinline__ float f16_rt(float v) {
    return __half2float(__float2half_rn(v));
}

__device__ __forceinline__ float ex2(float x) {
    float r;
    asm("ex2.approx.f32 %0, %1;" : "=f"(r) : "f"(x));
    return r;
}

// ---------------------------------------------------------------------------
// Pipelined split-fp16 GEMM — fine-grained tiles for makespan.
// CTA tile 128(m) x 64(n), 128 threads = 4 warps, warp tile m32 x n64
// (identical per-warp instruction mix to the previous 256-thread kernel).
// smem 2 stages x 30720 B = 61440 -> 3 CTAs/SM.
// nprod=3: AhBh + AlBh + AhBl (Q/K). nprod=2: AhBh + AlBh (V / out proj).
// QKV=1: grid.z selects weight/output; split fp16 epilogue (V: hi only).
// QKV=0: fp32 epilogue to C.
// ---------------------------------------------------------------------------
#define GK 1024
#define NCH (GK / 32)                // 32
#define TS 40
#define A_TILE_B 10240               // 128*40*2
#define B_TILE_B 5120                // 64*40*2
#define STAGE_B 30720                // Ah + Al + Bh + Bl
#define GEMM_SMEM (2 * STAGE_B)      // 61440

template <int QKV>
__global__ __launch_bounds__(128, 3) void gemm_pipe(
    const __half* __restrict__ Ah, const __half* __restrict__ Al,
    const __half* __restrict__ Bh, const __half* __restrict__ Bl,
    float* __restrict__ C, __half* __restrict__ H, __half* __restrict__ L) {
    extern __shared__ __align__(16) char gsm[];
    int nprod = 2;
    bool storeL = true;
    if (QKV) {
        const size_t zo = (size_t)blockIdx.z * D_MODEL * D_MODEL;
        Ah = g_xh; Al = g_xl;
        Bh = g_wh + zo; Bl = g_wl + zo;
        if (blockIdx.z == 0) { H = g_qh; L = g_ql; nprod = 3; }
        else if (blockIdx.z == 1) { H = g_kh; L = g_kl; nprod = 3; }
        else { H = g_vh; L = nullptr; storeL = false; }
    }

    const int tid = threadIdx.x;
    const int lane = tid & 31;
    const int wid = tid >> 5;            // 0..3, all along m
    const int mBase = wid * 32;
    const int bm = blockIdx.y * 128;
    const int bn = blockIdx.x * 64;      // n-tile of 64
    const uint32_t sb = smem_u32(gsm);

    float c[2][8][4];
#pragma unroll
    for (int mt = 0; mt < 2; mt++)
#pragma unroll
        for (int nt = 0; nt < 8; nt++)
#pragma unroll
            for (int j = 0; j < 4; j++) c[mt][nt][j] = 0.0f;

    const int a_row = lane & 15;
    const int a_koff = (lane >> 4) * 8;
    const int b_nrow = ((lane >> 4) * 8) + (lane & 7);
    const int b_koff = ((lane >> 3) & 1) * 8;

    auto issue = [&](int ch, int stage) {
        const int k0 = ch * 32;
        const __half* srcA[2] = {Ah + (size_t)bm * GK + k0, Al + (size_t)bm * GK + k0};
        const __half* srcB[2] = {Bh + (size_t)bn * GK + k0,
                                 Bl ? Bl + (size_t)bn * GK + k0 : nullptr};
        const uint32_t sbase = sb + stage * STAGE_B;
        // A tiles: 128 rows x 4 x 16B chunks = 512 cp16 per tile
#pragma unroll
        for (int t = 0; t < 2; t++) {
#pragma unroll
            for (int it = 0; it < 4; it++) {
                int idx = tid + it * 128;            // 0..511
                int r = idx >> 2, c16 = idx & 3;
                cp16(sbase + t * A_TILE_B + (r * TS + c16 * 8) * 2,
                     srcA[t] + (size_t)r * GK + c16 * 8);
            }
        }
        // B tiles: 64 rows x 4 chunks = 256 cp16 per tile
        const int nb = (nprod == 3) ? 2 : 1;
        for (int t = 0; t < nb; t++) {
#pragma unroll
            for (int it = 0; it < 2; it++) {
                int idx = tid + it * 128;            // 0..255
                int r = idx >> 2, c16 = idx & 3;
                cp16(sbase + 2 * A_TILE_B + t * B_TILE_B + (r * TS + c16 * 8) * 2,
                     srcB[t] + (size_t)r * GK + c16 * 8);
            }
        }
        CP_COMMIT();
    };

    issue(0, 0);

    for (int ch = 0; ch < NCH; ch++) {
        if (ch + 1 < NCH) {
            issue(ch + 1, (ch + 1) & 1);
            CP_WAIT(1);
        } else {
            CP_WAIT(0);
        }
        __syncthreads();
        const uint32_t base = sb + (ch & 1) * STAGE_B;
        const uint32_t bbase = base + 2 * A_TILE_B;

#pragma unroll
        for (int ks = 0; ks < 2; ks++) {
            uint32_t aH[2][4], aL[2][4], b[8][2];
#pragma unroll
            for (int mt = 0; mt < 2; mt++) {
                uint32_t off = ((mBase + mt * 16 + a_row) * TS + ks * 16 + a_koff) * 2;
                ldsm_x4(base + off, aH[mt][0], aH[mt][1], aH[mt][2], aH[mt][3]);
                ldsm_x4(base + A_TILE_B + off, aL[mt][0], aL[mt][1], aL[mt][2], aL[mt][3]);
            }
#pragma unroll
            for (int g = 0; g < 4; g++) {
                uint32_t off = ((g * 16 + b_nrow) * TS + ks * 16 + b_koff) * 2;
                ldsm_x4(bbase + off,
                        b[2 * g][0], b[2 * g][1], b[2 * g + 1][0], b[2 * g + 1][1]);
            }
#pragma unroll
            for (int mt = 0; mt < 2; mt++)
#pragma unroll
                for (int nt = 0; nt < 8; nt++) mma16816(c[mt][nt], aH[mt], b[nt]);
#pragma unroll
            for (int mt = 0; mt < 2; mt++)
#pragma unroll
                for (int nt = 0; nt < 8; nt++) mma16816(c[mt][nt], aL[mt], b[nt]);
            if (nprod == 3) {
#pragma unroll
                for (int g = 0; g < 4; g++) {
                    uint32_t off = ((g * 16 + b_nrow) * TS + ks * 16 + b_koff) * 2;
                    ldsm_x4(bbase + B_TILE_B + off,
                            b[2 * g][0], b[2 * g][1], b[2 * g + 1][0], b[2 * g + 1][1]);
                }
#pragma unroll
                for (int mt = 0; mt < 2; mt++)
#pragma unroll
                    for (int nt = 0; nt < 8; nt++) mma16816(c[mt][nt], aH[mt], b[nt]);
            }
        }
        __syncthreads();
    }

#pragma unroll
    for (int mt = 0; mt < 2; mt++) {
#pragma unroll
        for (int half = 0; half < 2; half++) {
            int row = bm + mBase + mt * 16 + (lane >> 2) + half * 8;
#pragma unroll
            for (int nt = 0; nt < 8; nt++) {
                int col = bn + nt * 8 + (lane & 3) * 2;
                float v0 = c[mt][nt][2 * half];
                float v1 = c[mt][nt][2 * half + 1];
                if (QKV) {
                    size_t off = (size_t)row * D_MODEL + col;
                    float h0 = f16_rt(v0), h1 = f16_rt(v1);
                    *(uint32_t*)(H + off) = pack_f16(h0, h1);
                    if (storeL)
                        *(uint32_t*)(L + off) = pack_f16(v0 - h0, v1 - h1);
                } else {
                    *(float2*)(C + (size_t)row * D_MODEL + col) = make_float2(v0, v1);
                }
            }
        }
    }
}

// ---------------------------------------------------------------------------
// Conversion kernels
// ---------------------------------------------------------------------------
__global__ __launch_bounds__(256) void split_fp32(const float* __restrict__ s,
                                                  __half* __restrict__ h,
                                                  __half* __restrict__ l) {
    int i = blockIdx.x * 256 + threadIdx.x;
    float4 v = ((const float4*)s)[i];
    float a[4] = {v.x, v.y, v.z, v.w};
    uint32_t hh[2], ll[2];
#pragma unroll
    for (int j = 0; j < 2; j++) {
        float h0 = f16_rt(a[2 * j]), h1 = f16_rt(a[2 * j + 1]);
        hh[j] = pack_f16(h0, h1);
        ll[j] = pack_f16(a[2 * j] - h0, a[2 * j + 1] - h1);
    }
    ((uint32_t*)h)[2 * i] = hh[0];
    ((uint32_t*)h)[2 * i + 1] = hh[1];
    ((uint32_t*)l)[2 * i] = ll[0];
    ((uint32_t*)l)[2 * i + 1] = ll[1];
}

__global__ __launch_bounds__(256) void transpose_split4(const float* __restrict__ w0,
                                                        const float* __restrict__ w1,
                                                        const float* __restrict__ w2,
                                                        const float* __restrict__ w3) {
    __shared__ float t[32][33];
    const int z = blockIdx.z;
    const float* W = z == 0 ? w0 : z == 1 ? w1 : z == 2 ? w2 : w3;
    __half* Th = g_wh + (size_t)z * D_MODEL * D_MODEL;
    __half* Tl = g_wl + (size_t)z * D_MODEL * D_MODEL;

    int x = blockIdx.x * 32 + threadIdx.x;
    int y0 = blockIdx.y * 32;
#pragma unroll
    for (int j = 0; j < 32; j += 8)
        t[threadIdx.y + j][threadIdx.x] = W[(size_t)(y0 + threadIdx.y + j) * D_MODEL + x];
    __syncthreads();
    int xo = blockIdx.y * 32 + threadIdx.x;
    int yo = blockIdx.x * 32;
#pragma unroll
    for (int j = 0; j < 32; j += 8) {
        float v = t[threadIdx.x][threadIdx.y + j];
        float hv = f16_rt(v);
        Th[(size_t)(yo + threadIdx.y + j) * D_MODEL + xo] = __float2half_rn(v);
        Tl[(size_t)(yo + threadIdx.y + j) * D_MODEL + xo] = __float2half_rn(v - hv);
    }
}

// ---------------------------------------------------------------------------
// Tensor-core causal flash attention, split-fp16, Q-in-registers.
// 64x64 tiles, 128 threads, 2-stage cp.async KV prefetch (Kh, Kl, Vh).
// One __syncthreads per iteration (prefetch issued after the sync; the sync
// itself proves prior-stage reads are complete). 3 CTAs/SM.
// ---------------------------------------------------------------------------
#define TS2 72
#define ATILE_B (64 * TS2 * 2)       // 9216 bytes per tile
#define KV_STAGE (3 * ATILE_B)       // 27648
#define ATTN_SMEM (2 * KV_STAGE)     // 55296

__global__ __launch_bounds__(128, 3) void attn_tc() {
    extern __shared__ __align__(16) char asmc[];
    const uint32_t sb = smem_u32(asmc);

    const int tid = threadIdx.x;
    const int lane = tid & 31;
    const int wq = tid >> 5;
    const int qb = gridDim.x - 1 - blockIdx.x;  // heavy blocks first
    const int bh = blockIdx.y;
    const int b = bh >> 4, h = bh & 15;

    const uint32_t a_off = ((wq * 16 + (lane & 15)) * TS2 + (lane >> 4) * 8) * 2;
    const uint32_t b_off = ((((lane >> 4) * 8) + (lane & 7)) * TS2 + ((lane >> 3) & 1) * 8) * 2;
    const uint32_t v_off = ((((lane >> 3) & 1) * 8 + (lane & 7)) * TS2 + (lane >> 4) * 8) * 2;

    // ---- stage Q through KV stage 0, hoist fragments to registers ----
    uint32_t qH[4][4], qL[4][4];
    {
        const size_t base = (size_t)(b * SEQ + qb * 64) * D_MODEL + h * 64;
#pragma unroll
        for (int it = 0; it < 4; it++) {
            int idx = tid + it * 128;
            int r = idx >> 3, c8 = (idx & 7) * 8;
            size_t g = base + (size_t)r * D_MODEL + c8;
            uint32_t so = (r * TS2 + c8) * 2;
            cp16(sb + so, g_qh + g);
            cp16(sb + ATILE_B + so, g_ql + g);
        }
        CP_COMMIT();
        CP_WAIT(0);
        __syncthreads();
#pragma unroll
        for (int ks = 0; ks < 4; ks++) {
            ldsm_x4(sb + a_off + ks * 32, qH[ks][0], qH[ks][1], qH[ks][2], qH[ks][3]);
            ldsm_x4(sb + ATILE_B + a_off + ks * 32, qL[ks][0], qL[ks][1], qL[ks][2], qL[ks][3]);
        }
        __syncthreads();  // all warps done reading Q before KV overwrites stage 0
    }

    auto issue_kv = [&](int kb, int stage) {
        const size_t base = (size_t)(b * SEQ + kb * 64) * D_MODEL + h * 64;
        const uint32_t kvb = sb + stage * KV_STAGE;
#pragma unroll
        for (int it = 0; it < 4; it++) {
            int idx = tid + it * 128;
            int r = idx >> 3, c8 = (idx & 7) * 8;
            size_t g = base + (size_t)r * D_MODEL + c8;
            uint32_t so = (r * TS2 + c8) * 2;
            cp16(kvb + so, g_kh + g);
            cp16(kvb + ATILE_B + so, g_kl + g);
            cp16(kvb + 2 * ATILE_B + so, g_vh + g);
        }
        CP_COMMIT();
    };

    issue_kv(0, 0);

    float O[8][4];
#pragma unroll
    for (int nt = 0; nt < 8; nt++)
#pragma unroll
        for (int j = 0; j < 4; j++) O[nt][j] = 0.0f;
    float mrow[2] = {-1e30f, -1e30f};
    float lrow[2] = {0.0f, 0.0f};

    const float scale2 = 0.03125f * 1.44269504088896f;  // scale * log2(e)

    const int row0 = qb * 64 + wq * 16 + (lane >> 2);

    for (int kb = 0; kb <= qb; kb++) {
        CP_WAIT(0);        // kb's stage complete (only group outstanding)
        __syncthreads();   // also proves all warps finished reading stage kb-1
        if (kb < qb) issue_kv(kb + 1, (kb + 1) & 1);  // overlaps with compute

        const uint32_t kvb = sb + (kb & 1) * KV_STAGE;
        const uint32_t SKH = kvb, SKL = kvb + ATILE_B, SVH = kvb + 2 * ATILE_B;

        // ---- S = Q @ K^T (3 products; Q from registers) ----
        float s[8][4];
#pragma unroll
        for (int nt = 0; nt < 8; nt++)
#pragma unroll
            for (int j = 0; j < 4; j++) s[nt][j] = 0.0f;

#pragma unroll
        for (int ks = 0; ks < 4; ks++) {
            uint32_t bk[8][2];
#pragma unroll
            for (int g = 0; g < 4; g++)
                ldsm_x4(SKH + b_off + g * 16 * TS2 * 2 + ks * 32,
                        bk[2 * g][0], bk[2 * g][1], bk[2 * g + 1][0], bk[2 * g + 1][1]);
#pragma unroll
            for (int nt = 0; nt < 8; nt++) mma16816(s[nt], qH[ks], bk[nt]);
#pragma unroll
            for (int nt = 0; nt < 8; nt++) mma16816(s[nt], qL[ks], bk[nt]);
#pragma unroll
            for (int g = 0; g < 4; g++)
                ldsm_x4(SKL + b_off + g * 16 * TS2 * 2 + ks * 32,
                        bk[2 * g][0], bk[2 * g][1], bk[2 * g + 1][0], bk[2 * g + 1][1]);
#pragma unroll
            for (int nt = 0; nt < 8; nt++) mma16816(s[nt], qH[ks], bk[nt]);
        }

        // ---- scale + mask + online softmax (base-2) ----
        const bool diag = (kb == qb);
#pragma unroll
        for (int i = 0; i < 2; i++) {
            const int rg = row0 + i * 8;
            float mx = -1e30f;
#pragma unroll
            for (int nt = 0; nt < 8; nt++) {
#pragma unroll
                for (int j = 0; j < 2; j++) {
                    float v = s[nt][2 * i + j] * scale2;
                    if (diag) {
                        int cg = kb * 64 + nt * 8 + (lane & 3) * 2 + j;
                        if (cg > rg) v = -1e30f;
                    }
                    s[nt][2 * i + j] = v;
                    mx = fmaxf(mx, v);
                }
            }
            mx = fmaxf(mx, __shfl_xor_sync(0xffffffffu, mx, 1));
            mx = fmaxf(mx, __shfl_xor_sync(0xffffffffu, mx, 2));
            float mn = fmaxf(mrow[i], mx);
            float alpha = ex2(mrow[i] - mn);
            mrow[i] = mn;
            float rs = 0.0f;
#pragma unroll
            for (int nt = 0; nt < 8; nt++) {
#pragma unroll
                for (int j = 0; j < 2; j++) {
                    float p = ex2(s[nt][2 * i + j] - mn);
                    s[nt][2 * i + j] = p;
                    rs += p;
                }
            }
            rs += __shfl_xor_sync(0xffffffffu, rs, 1);
            rs += __shfl_xor_sync(0xffffffffu, rs, 2);
            lrow[i] = lrow[i] * alpha + rs;
#pragma unroll
            for (int nt = 0; nt < 8; nt++) {
                O[nt][2 * i] *= alpha;
                O[nt][2 * i + 1] *= alpha;
            }
        }

        // ---- O += P @ V (2 products: PhVh + PlVh) ----
#pragma unroll
        for (int g = 0; g < 4; g++) {
            uint32_t pH[4], pL[4];
#pragma unroll
            for (int q2 = 0; q2 < 2; q2++) {
#pragma unroll
                for (int half = 0; half < 2; half++) {
                    float v0 = s[2 * g + q2][2 * half];
                    float v1 = s[2 * g + q2][2 * half + 1];
                    float h0 = f16_rt(v0), h1 = f16_rt(v1);
                    pH[2 * q2 + half] = pack_f16(h0, h1);
                    pL[2 * q2 + half] = pack_f16(v0 - h0, v1 - h1);
                }
            }
            uint32_t bv[8][2];
#pragma unroll
            for (int gn = 0; gn < 4; gn++)
                ldsm_x4_t(SVH + v_off + (g * 16 * TS2 + gn * 16) * 2,
                          bv[2 * gn][0], bv[2 * gn][1], bv[2 * gn + 1][0], bv[2 * gn + 1][1]);
#pragma unroll
            for (int nt = 0; nt < 8; nt++) mma16816(O[nt], pH, bv[nt]);
#pragma unroll
            for (int nt = 0; nt < 8; nt++) mma16816(O[nt], pL, bv[nt]);
        }
    }

    // ---- epilogue ----
#pragma unroll
    for (int i = 0; i < 2; i++) {
        float inv = 1.0f / lrow[i];
        size_t row = (size_t)(b * SEQ) + row0 + i * 8;
#pragma unroll
        for (int nt = 0; nt < 8; nt++) {
            size_t off = row * D_MODEL + h * 64 + nt * 8 + (lane & 3) * 2;
            float v0 = O[nt][2 * i] * inv;
            float v1 = O[nt][2 * i + 1] * inv;
            float h0 = f16_rt(v0), h1 = f16_rt(v1);
            *(uint32_t*)(g_ah + off) = pack_f16(h0, h1);
            *(uint32_t*)(g_al + off) = pack_f16(v0 - h0, v1 - h1);
        }
    }
}

// ---------------------------------------------------------------------------
// kernel_launch: x, qw, kw, vw, ow (fp32)
// ---------------------------------------------------------------------------
extern "C" void kernel_launch(void* const* d_in, const int* in_sizes, int n_in,
                              void* d_out, int out_size) {
    const float* x = (const float*)d_in[0];
    float* out = (float*)d_out;

    __half *xh, *xl, *ah, *al, *wh, *wl;
    cudaGetSymbolAddress((void**)&xh, g_xh);
    cudaGetSymbolAddress((void**)&xl, g_xl);
    cudaGetSymbolAddress((void**)&ah, g_ah);
    cudaGetSymbolAddress((void**)&al, g_al);
    cudaGetSymbolAddress((void**)&wh, g_wh);
    cudaGetSymbolAddress((void**)&wl, g_wl);

    cudaFuncSetAttribute(gemm_pipe<1>, cudaFuncAttributeMaxDynamicSharedMemorySize,
                         GEMM_SMEM);
    cudaFuncSetAttribute(gemm_pipe<0>, cudaFuncAttributeMaxDynamicSharedMemorySize,
                         GEMM_SMEM);
    cudaFuncSetAttribute(attn_tc, cudaFuncAttributeMaxDynamicSharedMemorySize,
                         ATTN_SMEM);

    // 1. split x into fp16 hi/lo
    split_fp32<<<(ROWS * D_MODEL / 4) / 256, 256>>>(x, xh, xl);
    // 2. transpose+split all 4 weights (one launch)
    transpose_split4<<<dim3(32, 32, 4), dim3(32, 8)>>>(
        (const float*)d_in[1], (const float*)d_in[2],
        (const float*)d_in[3], (const float*)d_in[4]);

    // 3. fused Q/K/V projections — fine-grained 128x64 tiles, 3 CTAs/SM
    //    (z slowest in dispatch order => light V tiles form the tail wave)
    gemm_pipe<1><<<dim3(D_MODEL / 64, ROWS / 128, 3), 128, GEMM_SMEM>>>(
        nullptr, nullptr, nullptr, nullptr, nullptr, nullptr, nullptr);

    // 4. tensor-core attention
    attn_tc<<<dim3(SEQ / 64, BATCH * N_HEADS), 128, ATTN_SMEM>>>();

    // 5. output projection (2-product, fp32 epilogue to d_out)
    gemm_pipe<0><<<dim3(D_MODEL / 64, ROWS / 128, 1), 128, GEMM_SMEM>>>(
        ah, al, wh + 3u * D_MODEL * D_MODEL, nullptr, out, nullptr, nullptr);
}

// round 16
// speedup vs baseline: 1.4435x; 1.1865x over previous
#include <cuda_runtime.h>
#include <cuda_fp16.h>
#include <cstdint>
#include <cstddef>

#define D_MODEL 1024
#define N_HEADS 16
#define HEAD_DIM 64
#define BATCH 2
#define SEQ 2048
#define ROWS (BATCH * SEQ)   // 4096

// ---------------- scratch (__device__ globals; allocation-free rule) -------
__device__ __half g_xh[ROWS * D_MODEL];
__device__ __half g_xl[ROWS * D_MODEL];
__device__ __half g_qh[ROWS * D_MODEL];
__device__ __half g_ql[ROWS * D_MODEL];
__device__ __half g_kh[ROWS * D_MODEL];
__device__ __half g_kl[ROWS * D_MODEL];
__device__ __half g_vh[ROWS * D_MODEL];
__device__ __half g_ah[ROWS * D_MODEL];
__device__ __half g_wh[4 * D_MODEL * D_MODEL];  // transposed [N,K]
__device__ __half g_wl[4 * D_MODEL * D_MODEL];  // lo only used by Q/K proj

// ---------------- helpers --------------------------------------------------
__device__ __forceinline__ uint32_t smem_u32(const void* p) {
    uint32_t a;
    asm("{ .reg .u64 t; cvta.to.shared.u64 t, %1; cvt.u32.u64 %0, t; }"
        : "=r"(a) : "l"(p));
    return a;
}

__device__ __forceinline__ void cp16(uint32_t s, const void* g) {
    asm volatile("cp.async.cg.shared.global [%0], [%1], 16;" :: "r"(s), "l"(g));
}
#define CP_COMMIT() asm volatile("cp.async.commit_group;" ::: "memory")
#define CP_WAIT(n)  asm volatile("cp.async.wait_group %0;" :: "n"(n) : "memory")

__device__ __forceinline__ void ldsm_x4(uint32_t addr, uint32_t& r0, uint32_t& r1,
                                        uint32_t& r2, uint32_t& r3) {
    asm volatile("ldmatrix.sync.aligned.m8n8.x4.shared.b16 {%0,%1,%2,%3}, [%4];"
                 : "=r"(r0), "=r"(r1), "=r"(r2), "=r"(r3) : "r"(addr));
}

__device__ __forceinline__ void ldsm_x4_t(uint32_t addr, uint32_t& r0, uint32_t& r1,
                                          uint32_t& r2, uint32_t& r3) {
    asm volatile("ldmatrix.sync.aligned.m8n8.x4.trans.shared.b16 {%0,%1,%2,%3}, [%4];"
                 : "=r"(r0), "=r"(r1), "=r"(r2), "=r"(r3) : "r"(addr));
}

__device__ __forceinline__ void mma16816(float* c, const uint32_t* a, const uint32_t* b) {
    asm volatile(
        "mma.sync.aligned.m16n8k16.row.col.f32.f16.f16.f32 "
        "{%0,%1,%2,%3},{%4,%5,%6,%7},{%8,%9},{%0,%1,%2,%3};"
        : "+f"(c[0]), "+f"(c[1]), "+f"(c[2]), "+f"(c[3])
        : "r"(a[0]), "r"(a[1]), "r"(a[2]), "r"(a[3]), "r"(b[0]), "r"(b[1]));
}

__device__ __forceinline__ uint32_t pack_f16(float lo, float hi) {
    uint32_t r;
    asm("cvt.rn.f16x2.f32 %0, %1, %2;" : "=r"(r) : "f"(hi), "f"(lo));
    return r;
}

__device__ __forceinline__ float f16_rt(float v) {
    return __half2float(__float2half_rn(v));
}

__device__ __forceinline__ float ex2(float x) {
    float r;
    asm("ex2.approx.f32 %0, %1;" : "=f"(r) : "f"(x));
    return r;
}

// ---------------------------------------------------------------------------
// Pipelined split-fp16 GEMM. CTA tile 128(m) x 64(n), 128 threads (4 warps,
// warp tile m32 x n64). smem 2 stages x 30720 B -> 3 CTAs/SM.
// nprod=3: AhBh + AlBh + AhBl (Q/K proj)
// nprod=1: AhBh only           (V proj, output proj)
// QKV=1: grid.z selects weight/output; split fp16 epilogue (Q/K: hi+lo,
//        V: hi only). QKV=0: fp32 epilogue to C, 1 product.
// ---------------------------------------------------------------------------
#define GK 1024
#define NCH (GK / 32)                // 32
#define TS 40
#define A_TILE_B 10240               // 128*40*2
#define B_TILE_B 5120                // 64*40*2
#define STAGE_B 30720                // Ah + Al + Bh + Bl (max layout)
#define GEMM_SMEM (2 * STAGE_B)      // 61440

template <int QKV>
__global__ __launch_bounds__(128, 3) void gemm_pipe(
    const __half* __restrict__ Ah, const __half* __restrict__ Al,
    const __half* __restrict__ Bh, const __half* __restrict__ Bl,
    float* __restrict__ C, __half* __restrict__ H, __half* __restrict__ L) {
    extern __shared__ __align__(16) char gsm[];
    int nprod = 1;
    bool storeL = false;
    if (QKV) {
        const size_t zo = (size_t)blockIdx.z * D_MODEL * D_MODEL;
        Ah = g_xh; Al = g_xl;
        Bh = g_wh + zo; Bl = g_wl + zo;
        if (blockIdx.z == 0) { H = g_qh; L = g_ql; nprod = 3; storeL = true; }
        else if (blockIdx.z == 1) { H = g_kh; L = g_kl; nprod = 3; storeL = true; }
        else { H = g_vh; L = nullptr; }     // V: 1 product, hi only
    }

    const int tid = threadIdx.x;
    const int lane = tid & 31;
    const int wid = tid >> 5;            // 0..3, all along m
    const int mBase = wid * 32;
    const int bm = blockIdx.y * 128;
    const int bn = blockIdx.x * 64;      // n-tile of 64
    const uint32_t sb = smem_u32(gsm);

    float c[2][8][4];
#pragma unroll
    for (int mt = 0; mt < 2; mt++)
#pragma unroll
        for (int nt = 0; nt < 8; nt++)
#pragma unroll
            for (int j = 0; j < 4; j++) c[mt][nt][j] = 0.0f;

    const int a_row = lane & 15;
    const int a_koff = (lane >> 4) * 8;
    const int b_nrow = ((lane >> 4) * 8) + (lane & 7);
    const int b_koff = ((lane >> 3) & 1) * 8;

    auto issue = [&](int ch, int stage) {
        const int k0 = ch * 32;
        const uint32_t sbase = sb + stage * STAGE_B;
        // Ah tile: 128 rows x 4 x 16B chunks = 512 cp16
        {
            const __half* src = Ah + (size_t)bm * GK + k0;
#pragma unroll
            for (int it = 0; it < 4; it++) {
                int idx = tid + it * 128;
                int r = idx >> 2, c16 = idx & 3;
                cp16(sbase + (r * TS + c16 * 8) * 2, src + (size_t)r * GK + c16 * 8);
            }
        }
        if (nprod >= 2) {
            const __half* src = Al + (size_t)bm * GK + k0;
#pragma unroll
            for (int it = 0; it < 4; it++) {
                int idx = tid + it * 128;
                int r = idx >> 2, c16 = idx & 3;
                cp16(sbase + A_TILE_B + (r * TS + c16 * 8) * 2,
                     src + (size_t)r * GK + c16 * 8);
            }
        }
        // Bh tile: 64 rows x 4 chunks = 256 cp16
        {
            const __half* src = Bh + (size_t)bn * GK + k0;
#pragma unroll
            for (int it = 0; it < 2; it++) {
                int idx = tid + it * 128;
                int r = idx >> 2, c16 = idx & 3;
                cp16(sbase + 2 * A_TILE_B + (r * TS + c16 * 8) * 2,
                     src + (size_t)r * GK + c16 * 8);
            }
        }
        if (nprod == 3) {
            const __half* src = Bl + (size_t)bn * GK + k0;
#pragma unroll
            for (int it = 0; it < 2; it++) {
                int idx = tid + it * 128;
                int r = idx >> 2, c16 = idx & 3;
                cp16(sbase + 2 * A_TILE_B + B_TILE_B + (r * TS + c16 * 8) * 2,
                     src + (size_t)r * GK + c16 * 8);
            }
        }
        CP_COMMIT();
    };

    issue(0, 0);

    for (int ch = 0; ch < NCH; ch++) {
        if (ch + 1 < NCH) {
            issue(ch + 1, (ch + 1) & 1);
            CP_WAIT(1);
        } else {
            CP_WAIT(0);
        }
        __syncthreads();
        const uint32_t base = sb + (ch & 1) * STAGE_B;
        const uint32_t bbase = base + 2 * A_TILE_B;

#pragma unroll
        for (int ks = 0; ks < 2; ks++) {
            uint32_t aH[2][4], b[8][2];
#pragma unroll
            for (int mt = 0; mt < 2; mt++) {
                uint32_t off = ((mBase + mt * 16 + a_row) * TS + ks * 16 + a_koff) * 2;
                ldsm_x4(base + off, aH[mt][0], aH[mt][1], aH[mt][2], aH[mt][3]);
            }
#pragma unroll
            for (int g = 0; g < 4; g++) {
                uint32_t off = ((g * 16 + b_nrow) * TS + ks * 16 + b_koff) * 2;
                ldsm_x4(bbase + off,
                        b[2 * g][0], b[2 * g][1], b[2 * g + 1][0], b[2 * g + 1][1]);
            }
#pragma unroll
            for (int mt = 0; mt < 2; mt++)
#pragma unroll
                for (int nt = 0; nt < 8; nt++) mma16816(c[mt][nt], aH[mt], b[nt]);
            if (nprod >= 2) {
                uint32_t aL[2][4];
#pragma unroll
                for (int mt = 0; mt < 2; mt++) {
                    uint32_t off = ((mBase + mt * 16 + a_row) * TS + ks * 16 + a_koff) * 2;
                    ldsm_x4(base + A_TILE_B + off,
                            aL[mt][0], aL[mt][1], aL[mt][2], aL[mt][3]);
                }
#pragma unroll
                for (int mt = 0; mt < 2; mt++)
#pragma unroll
                    for (int nt = 0; nt < 8; nt++) mma16816(c[mt][nt], aL[mt], b[nt]);
            }
            if (nprod == 3) {
#pragma unroll
                for (int g = 0; g < 4; g++) {
                    uint32_t off = ((g * 16 + b_nrow) * TS + ks * 16 + b_koff) * 2;
                    ldsm_x4(bbase + B_TILE_B + off,
                            b[2 * g][0], b[2 * g][1], b[2 * g + 1][0], b[2 * g + 1][1]);
                }
#pragma unroll
                for (int mt = 0; mt < 2; mt++)
#pragma unroll
                    for (int nt = 0; nt < 8; nt++) mma16816(c[mt][nt], aH[mt], b[nt]);
            }
        }
        __syncthreads();
    }

#pragma unroll
    for (int mt = 0; mt < 2; mt++) {
#pragma unroll
        for (int half = 0; half < 2; half++) {
            int row = bm + mBase + mt * 16 + (lane >> 2) + half * 8;
#pragma unroll
            for (int nt = 0; nt < 8; nt++) {
                int col = bn + nt * 8 + (lane & 3) * 2;
                float v0 = c[mt][nt][2 * half];
                float v1 = c[mt][nt][2 * half + 1];
                if (QKV) {
                    size_t off = (size_t)row * D_MODEL + col;
                    float h0 = f16_rt(v0), h1 = f16_rt(v1);
                    *(uint32_t*)(H + off) = pack_f16(h0, h1);
                    if (storeL)
                        *(uint32_t*)(L + off) = pack_f16(v0 - h0, v1 - h1);
                } else {
                    *(float2*)(C + (size_t)row * D_MODEL + col) = make_float2(v0, v1);
                }
            }
        }
    }
}

// ---------------------------------------------------------------------------
// Conversion kernels
// ---------------------------------------------------------------------------
__global__ __launch_bounds__(256) void split_fp32(const float* __restrict__ s,
                                                  __half* __restrict__ h,
                                                  __half* __restrict__ l) {
    int i = blockIdx.x * 256 + threadIdx.x;
    float4 v = ((const float4*)s)[i];
    float a[4] = {v.x, v.y, v.z, v.w};
    uint32_t hh[2], ll[2];
#pragma unroll
    for (int j = 0; j < 2; j++) {
        float h0 = f16_rt(a[2 * j]), h1 = f16_rt(a[2 * j + 1]);
        hh[j] = pack_f16(h0, h1);
        ll[j] = pack_f16(a[2 * j] - h0, a[2 * j + 1] - h1);
    }
    ((uint32_t*)h)[2 * i] = hh[0];
    ((uint32_t*)h)[2 * i + 1] = hh[1];
    ((uint32_t*)l)[2 * i] = ll[0];
    ((uint32_t*)l)[2 * i + 1] = ll[1];
}

__global__ __launch_bounds__(256) void transpose_split4(const float* __restrict__ w0,
                                                        const float* __restrict__ w1,
                                                        const float* __restrict__ w2,
                                                        const float* __restrict__ w3) {
    __shared__ float t[32][33];
    const int z = blockIdx.z;
    const float* W = z == 0 ? w0 : z == 1 ? w1 : z == 2 ? w2 : w3;
    __half* Th = g_wh + (size_t)z * D_MODEL * D_MODEL;
    __half* Tl = g_wl + (size_t)z * D_MODEL * D_MODEL;

    int x = blockIdx.x * 32 + threadIdx.x;
    int y0 = blockIdx.y * 32;
#pragma unroll
    for (int j = 0; j < 32; j += 8)
        t[threadIdx.y + j][threadIdx.x] = W[(size_t)(y0 + threadIdx.y + j) * D_MODEL + x];
    __syncthreads();
    int xo = blockIdx.y * 32 + threadIdx.x;
    int yo = blockIdx.x * 32;
#pragma unroll
    for (int j = 0; j < 32; j += 8) {
        float v = t[threadIdx.x][threadIdx.y + j];
        float hv = f16_rt(v);
        Th[(size_t)(yo + threadIdx.y + j) * D_MODEL + xo] = __float2half_rn(v);
        Tl[(size_t)(yo + threadIdx.y + j) * D_MODEL + xo] = __float2half_rn(v - hv);
    }
}

// ---------------------------------------------------------------------------
// Tensor-core causal flash attention, split-fp16, Q-in-registers.
// 64x64 tiles, 128 threads, 2-stage cp.async KV prefetch (Kh, Kl, Vh).
// Epilogue writes fp16-hi only (out-proj is 1-product). 3 CTAs/SM.
// ---------------------------------------------------------------------------
#define TS2 72
#define ATILE_B (64 * TS2 * 2)       // 9216 bytes per tile
#define KV_STAGE (3 * ATILE_B)       // 27648
#define ATTN_SMEM (2 * KV_STAGE)     // 55296

__global__ __launch_bounds__(128, 3) void attn_tc() {
    extern __shared__ __align__(16) char asmc[];
    const uint32_t sb = smem_u32(asmc);

    const int tid = threadIdx.x;
    const int lane = tid & 31;
    const int wq = tid >> 5;
    const int qb = gridDim.x - 1 - blockIdx.x;  // heavy blocks first
    const int bh = blockIdx.y;
    const int b = bh >> 4, h = bh & 15;

    const uint32_t a_off = ((wq * 16 + (lane & 15)) * TS2 + (lane >> 4) * 8) * 2;
    const uint32_t b_off = ((((lane >> 4) * 8) + (lane & 7)) * TS2 + ((lane >> 3) & 1) * 8) * 2;
    const uint32_t v_off = ((((lane >> 3) & 1) * 8 + (lane & 7)) * TS2 + (lane >> 4) * 8) * 2;

    // ---- stage Q through KV stage 0, hoist fragments to registers ----
    uint32_t qH[4][4], qL[4][4];
    {
        const size_t base = (size_t)(b * SEQ + qb * 64) * D_MODEL + h * 64;
#pragma unroll
        for (int it = 0; it < 4; it++) {
            int idx = tid + it * 128;
            int r = idx >> 3, c8 = (idx & 7) * 8;
            size_t g = base + (size_t)r * D_MODEL + c8;
            uint32_t so = (r * TS2 + c8) * 2;
            cp16(sb + so, g_qh + g);
            cp16(sb + ATILE_B + so, g_ql + g);
        }
        CP_COMMIT();
        CP_WAIT(0);
        __syncthreads();
#pragma unroll
        for (int ks = 0; ks < 4; ks++) {
            ldsm_x4(sb + a_off + ks * 32, qH[ks][0], qH[ks][1], qH[ks][2], qH[ks][3]);
            ldsm_x4(sb + ATILE_B + a_off + ks * 32, qL[ks][0], qL[ks][1], qL[ks][2], qL[ks][3]);
        }
        __syncthreads();  // all warps done reading Q before KV overwrites stage 0
    }

    auto issue_kv = [&](int kb, int stage) {
        const size_t base = (size_t)(b * SEQ + kb * 64) * D_MODEL + h * 64;
        const uint32_t kvb = sb + stage * KV_STAGE;
#pragma unroll
        for (int it = 0; it < 4; it++) {
            int idx = tid + it * 128;
            int r = idx >> 3, c8 = (idx & 7) * 8;
            size_t g = base + (size_t)r * D_MODEL + c8;
            uint32_t so = (r * TS2 + c8) * 2;
            cp16(kvb + so, g_kh + g);
            cp16(kvb + ATILE_B + so, g_kl + g);
            cp16(kvb + 2 * ATILE_B + so, g_vh + g);
        }
        CP_COMMIT();
    };

    issue_kv(0, 0);

    float O[8][4];
#pragma unroll
    for (int nt = 0; nt < 8; nt++)
#pragma unroll
        for (int j = 0; j < 4; j++) O[nt][j] = 0.0f;
    float mrow[2] = {-1e30f, -1e30f};
    float lrow[2] = {0.0f, 0.0f};

    const float scale2 = 0.03125f * 1.44269504088896f;  // scale * log2(e)

    const int row0 = qb * 64 + wq * 16 + (lane >> 2);

    for (int kb = 0; kb <= qb; kb++) {
        CP_WAIT(0);
        __syncthreads();
        if (kb < qb) issue_kv(kb + 1, (kb + 1) & 1);  // overlaps with compute

        const uint32_t kvb = sb + (kb & 1) * KV_STAGE;
        const uint32_t SKH = kvb, SKL = kvb + ATILE_B, SVH = kvb + 2 * ATILE_B;

        // ---- S = Q @ K^T (3 products; Q from registers) ----
        float s[8][4];
#pragma unroll
        for (int nt = 0; nt < 8; nt++)
#pragma unroll
            for (int j = 0; j < 4; j++) s[nt][j] = 0.0f;

#pragma unroll
        for (int ks = 0; ks < 4; ks++) {
            uint32_t bk[8][2];
#pragma unroll
            for (int g = 0; g < 4; g++)
                ldsm_x4(SKH + b_off + g * 16 * TS2 * 2 + ks * 32,
                        bk[2 * g][0], bk[2 * g][1], bk[2 * g + 1][0], bk[2 * g + 1][1]);
#pragma unroll
            for (int nt = 0; nt < 8; nt++) mma16816(s[nt], qH[ks], bk[nt]);
#pragma unroll
            for (int nt = 0; nt < 8; nt++) mma16816(s[nt], qL[ks], bk[nt]);
#pragma unroll
            for (int g = 0; g < 4; g++)
                ldsm_x4(SKL + b_off + g * 16 * TS2 * 2 + ks * 32,
                        bk[2 * g][0], bk[2 * g][1], bk[2 * g + 1][0], bk[2 * g + 1][1]);
#pragma unroll
            for (int nt = 0; nt < 8; nt++) mma16816(s[nt], qH[ks], bk[nt]);
        }

        // ---- scale + mask + online softmax (base-2) ----
        const bool diag = (kb == qb);
#pragma unroll
        for (int i = 0; i < 2; i++) {
            const int rg = row0 + i * 8;
            float mx = -1e30f;
#pragma unroll
            for (int nt = 0; nt < 8; nt++) {
#pragma unroll
                for (int j = 0; j < 2; j++) {
                    float v = s[nt][2 * i + j] * scale2;
                    if (diag) {
                        int cg = kb * 64 + nt * 8 + (lane & 3) * 2 + j;
                        if (cg > rg) v = -1e30f;
                    }
                    s[nt][2 * i + j] = v;
                    mx = fmaxf(mx, v);
                }
            }
            mx = fmaxf(mx, __shfl_xor_sync(0xffffffffu, mx, 1));
            mx = fmaxf(mx, __shfl_xor_sync(0xffffffffu, mx, 2));
            float mn = fmaxf(mrow[i], mx);
            float alpha = ex2(mrow[i] - mn);
            mrow[i] = mn;
            float rs = 0.0f;
#pragma unroll
            for (int nt = 0; nt < 8; nt++) {
#pragma unroll
                for (int j = 0; j < 2; j++) {
                    float p = ex2(s[nt][2 * i + j] - mn);
                    s[nt][2 * i + j] = p;
                    rs += p;
                }
            }
            rs += __shfl_xor_sync(0xffffffffu, rs, 1);
            rs += __shfl_xor_sync(0xffffffffu, rs, 2);
            lrow[i] = lrow[i] * alpha + rs;
#pragma unroll
            for (int nt = 0; nt < 8; nt++) {
                O[nt][2 * i] *= alpha;
                O[nt][2 * i + 1] *= alpha;
            }
        }

        // ---- O += P @ V (2 products: PhVh + PlVh) ----
#pragma unroll
        for (int g = 0; g < 4; g++) {
            uint32_t pH[4], pL[4];
#pragma unroll
            for (int q2 = 0; q2 < 2; q2++) {
#pragma unroll
                for (int half = 0; half < 2; half++) {
                    float v0 = s[2 * g + q2][2 * half];
                    float v1 = s[2 * g + q2][2 * half + 1];
                    float h0 = f16_rt(v0), h1 = f16_rt(v1);
                    pH[2 * q2 + half] = pack_f16(h0, h1);
                    pL[2 * q2 + half] = pack_f16(v0 - h0, v1 - h1);
                }
            }
            uint32_t bv[8][2];
#pragma unroll
            for (int gn = 0; gn < 4; gn++)
                ldsm_x4_t(SVH + v_off + (g * 16 * TS2 + gn * 16) * 2,
                          bv[2 * gn][0], bv[2 * gn][1], bv[2 * gn + 1][0], bv[2 * gn + 1][1]);
#pragma unroll
            for (int nt = 0; nt < 8; nt++) mma16816(O[nt], pH, bv[nt]);
#pragma unroll
            for (int nt = 0; nt < 8; nt++) mma16816(O[nt], pL, bv[nt]);
        }
    }

    // ---- epilogue: fp16-hi only (out-proj is 1-product) ----
#pragma unroll
    for (int i = 0; i < 2; i++) {
        float inv = 1.0f / lrow[i];
        size_t row = (size_t)(b * SEQ) + row0 + i * 8;
#pragma unroll
        for (int nt = 0; nt < 8; nt++) {
            size_t off = row * D_MODEL + h * 64 + nt * 8 + (lane & 3) * 2;
            float v0 = O[nt][2 * i] * inv;
            float v1 = O[nt][2 * i + 1] * inv;
            *(uint32_t*)(g_ah + off) = pack_f16(f16_rt(v0), f16_rt(v1));
        }
    }
}

// ---------------------------------------------------------------------------
// kernel_launch: x, qw, kw, vw, ow (fp32)
// ---------------------------------------------------------------------------
extern "C" void kernel_launch(void* const* d_in, const int* in_sizes, int n_in,
                              void* d_out, int out_size) {
    const float* x = (const float*)d_in[0];
    float* out = (float*)d_out;

    __half *xh, *xl, *ah, *wh, *wl;
    cudaGetSymbolAddress((void**)&xh, g_xh);
    cudaGetSymbolAddress((void**)&xl, g_xl);
    cudaGetSymbolAddress((void**)&ah, g_ah);
    cudaGetSymbolAddress((void**)&wh, g_wh);
    cudaGetSymbolAddress((void**)&wl, g_wl);

    cudaFuncSetAttribute(gemm_pipe<1>, cudaFuncAttributeMaxDynamicSharedMemorySize,
                         GEMM_SMEM);
    cudaFuncSetAttribute(gemm_pipe<0>, cudaFuncAttributeMaxDynamicSharedMemorySize,
                         GEMM_SMEM);
    cudaFuncSetAttribute(attn_tc, cudaFuncAttributeMaxDynamicSharedMemorySize,
                         ATTN_SMEM);

    // 1. split x into fp16 hi/lo
    split_fp32<<<(ROWS * D_MODEL / 4) / 256, 256>>>(x, xh, xl);
    // 2. transpose+split all 4 weights (one launch)
    transpose_split4<<<dim3(32, 32, 4), dim3(32, 8)>>>(
        (const float*)d_in[1], (const float*)d_in[2],
        (const float*)d_in[3], (const float*)d_in[4]);

    // 3. fused Q/K/V projections (Q,K 3-product; V 1-product)
    gemm_pipe<1><<<dim3(D_MODEL / 64, ROWS / 128, 3), 128, GEMM_SMEM>>>(
        nullptr, nullptr, nullptr, nullptr, nullptr, nullptr, nullptr);

    // 4. tensor-core attention
    attn_tc<<<dim3(SEQ / 64, BATCH * N_HEADS), 128, ATTN_SMEM>>>();

    // 5. output projection (1-product: ah @ owh, fp32 epilogue to d_out)
    gemm_pipe<0><<<dim3(D_MODEL / 64, ROWS / 128, 1), 128, GEMM_SMEM>>>(
        ah, nullptr, wh + 3u * D_MODEL * D_MODEL, nullptr, out, nullptr, nullptr);
}

// round 17
// speedup vs baseline: 1.5279x; 1.0585x over previous
#include <cuda_runtime.h>
#include <cuda_fp16.h>
#include <cstdint>
#include <cstddef>

#define D_MODEL 1024
#define N_HEADS 16
#define HEAD_DIM 64
#define BATCH 2
#define SEQ 2048
#define ROWS (BATCH * SEQ)   // 4096

// ---------------- scratch (__device__ globals; allocation-free rule) -------
__device__ __half g_xh[ROWS * D_MODEL];
__device__ __half g_xl[ROWS * D_MODEL];
__device__ __half g_qh[ROWS * D_MODEL];
__device__ __half g_ql[ROWS * D_MODEL];
__device__ __half g_kh[ROWS * D_MODEL];
__device__ __half g_kl[ROWS * D_MODEL];
__device__ __half g_vh[ROWS * D_MODEL];
__device__ __half g_ah[ROWS * D_MODEL];
__device__ __half g_wh[4 * D_MODEL * D_MODEL];  // transposed [N,K]
__device__ __half g_wl[4 * D_MODEL * D_MODEL];  // lo only used by Q/K proj

// ---------------- helpers --------------------------------------------------
__device__ __forceinline__ uint32_t smem_u32(const void* p) {
    uint32_t a;
    asm("{ .reg .u64 t; cvta.to.shared.u64 t, %1; cvt.u32.u64 %0, t; }"
        : "=r"(a) : "l"(p));
    return a;
}

__device__ __forceinline__ void cp16(uint32_t s, const void* g) {
    asm volatile("cp.async.cg.shared.global [%0], [%1], 16;" :: "r"(s), "l"(g));
}
#define CP_COMMIT() asm volatile("cp.async.commit_group;" ::: "memory")
#define CP_WAIT(n)  asm volatile("cp.async.wait_group %0;" :: "n"(n) : "memory")

__device__ __forceinline__ void ldsm_x4(uint32_t addr, uint32_t& r0, uint32_t& r1,
                                        uint32_t& r2, uint32_t& r3) {
    asm volatile("ldmatrix.sync.aligned.m8n8.x4.shared.b16 {%0,%1,%2,%3}, [%4];"
                 : "=r"(r0), "=r"(r1), "=r"(r2), "=r"(r3) : "r"(addr));
}

__device__ __forceinline__ void ldsm_x4_t(uint32_t addr, uint32_t& r0, uint32_t& r1,
                                          uint32_t& r2, uint32_t& r3) {
    asm volatile("ldmatrix.sync.aligned.m8n8.x4.trans.shared.b16 {%0,%1,%2,%3}, [%4];"
                 : "=r"(r0), "=r"(r1), "=r"(r2), "=r"(r3) : "r"(addr));
}

__device__ __forceinline__ void mma16816(float* c, const uint32_t* a, const uint32_t* b) {
    asm volatile(
        "mma.sync.aligned.m16n8k16.row.col.f32.f16.f16.f32 "
        "{%0,%1,%2,%3},{%4,%5,%6,%7},{%8,%9},{%0,%1,%2,%3};"
        : "+f"(c[0]), "+f"(c[1]), "+f"(c[2]), "+f"(c[3])
        : "r"(a[0]), "r"(a[1]), "r"(a[2]), "r"(a[3]), "r"(b[0]), "r"(b[1]));
}

__device__ __forceinline__ uint32_t pack_f16(float lo, float hi) {
    uint32_t r;
    asm("cvt.rn.f16x2.f32 %0, %1, %2;" : "=r"(r) : "f"(hi), "f"(lo));
    return r;
}

__device__ __forceinline__ float f16_rt(float v) {
    return __half2float(__float2half_rn(v));
}

__device__ __forceinline__ float ex2(float x) {
    float r;
    asm("ex2.approx.f32 %0, %1;" : "=f"(r) : "f"(x));
    return r;
}

// ---------------------------------------------------------------------------
// Pipelined split-fp16 GEMM. CTA tile 128(m) x 64(n), 128 threads (4 warps,
// warp tile m32 x n64). smem 2 stages x 30720 B -> 3 CTAs/SM.
// nprod=3: AhBh + AlBh + AhBl (Q/K proj)
// nprod=1: AhBh only           (V proj, output proj)
// QKV=1: grid.z selects weight/output; split fp16 epilogue (Q/K: hi+lo,
//        V: hi only). QKV=0: fp32 epilogue to C, 1 product.
// ---------------------------------------------------------------------------
#define GK 1024
#define NCH (GK / 32)                // 32
#define TS 40
#define A_TILE_B 10240               // 128*40*2
#define B_TILE_B 5120                // 64*40*2
#define STAGE_B 30720                // Ah + Al + Bh + Bl (max layout)
#define GEMM_SMEM (2 * STAGE_B)      // 61440

template <int QKV>
__global__ __launch_bounds__(128, 3) void gemm_pipe(
    const __half* __restrict__ Ah, const __half* __restrict__ Al,
    const __half* __restrict__ Bh, const __half* __restrict__ Bl,
    float* __restrict__ C, __half* __restrict__ H, __half* __restrict__ L) {
    extern __shared__ __align__(16) char gsm[];
    int nprod = 1;
    bool storeL = false;
    if (QKV) {
        const size_t zo = (size_t)blockIdx.z * D_MODEL * D_MODEL;
        Ah = g_xh; Al = g_xl;
        Bh = g_wh + zo; Bl = g_wl + zo;
        if (blockIdx.z == 0) { H = g_qh; L = g_ql; nprod = 3; storeL = true; }
        else if (blockIdx.z == 1) { H = g_kh; L = g_kl; nprod = 3; storeL = true; }
        else { H = g_vh; L = nullptr; }     // V: 1 product, hi only
    }

    const int tid = threadIdx.x;
    const int lane = tid & 31;
    const int wid = tid >> 5;            // 0..3, all along m
    const int mBase = wid * 32;
    const int bm = blockIdx.y * 128;
    const int bn = blockIdx.x * 64;      // n-tile of 64
    const uint32_t sb = smem_u32(gsm);

    float c[2][8][4];
#pragma unroll
    for (int mt = 0; mt < 2; mt++)
#pragma unroll
        for (int nt = 0; nt < 8; nt++)
#pragma unroll
            for (int j = 0; j < 4; j++) c[mt][nt][j] = 0.0f;

    const int a_row = lane & 15;
    const int a_koff = (lane >> 4) * 8;
    const int b_nrow = ((lane >> 4) * 8) + (lane & 7);
    const int b_koff = ((lane >> 3) & 1) * 8;

    auto issue = [&](int ch, int stage) {
        const int k0 = ch * 32;
        const uint32_t sbase = sb + stage * STAGE_B;
        {
            const __half* src = Ah + (size_t)bm * GK + k0;
#pragma unroll
            for (int it = 0; it < 4; it++) {
                int idx = tid + it * 128;
                int r = idx >> 2, c16 = idx & 3;
                cp16(sbase + (r * TS + c16 * 8) * 2, src + (size_t)r * GK + c16 * 8);
            }
        }
        if (nprod >= 2) {
            const __half* src = Al + (size_t)bm * GK + k0;
#pragma unroll
            for (int it = 0; it < 4; it++) {
                int idx = tid + it * 128;
                int r = idx >> 2, c16 = idx & 3;
                cp16(sbase + A_TILE_B + (r * TS + c16 * 8) * 2,
                     src + (size_t)r * GK + c16 * 8);
            }
        }
        {
            const __half* src = Bh + (size_t)bn * GK + k0;
#pragma unroll
            for (int it = 0; it < 2; it++) {
                int idx = tid + it * 128;
                int r = idx >> 2, c16 = idx & 3;
                cp16(sbase + 2 * A_TILE_B + (r * TS + c16 * 8) * 2,
                     src + (size_t)r * GK + c16 * 8);
            }
        }
        if (nprod == 3) {
            const __half* src = Bl + (size_t)bn * GK + k0;
#pragma unroll
            for (int it = 0; it < 2; it++) {
                int idx = tid + it * 128;
                int r = idx >> 2, c16 = idx & 3;
                cp16(sbase + 2 * A_TILE_B + B_TILE_B + (r * TS + c16 * 8) * 2,
                     src + (size_t)r * GK + c16 * 8);
            }
        }
        CP_COMMIT();
    };

    issue(0, 0);

    for (int ch = 0; ch < NCH; ch++) {
        if (ch + 1 < NCH) {
            issue(ch + 1, (ch + 1) & 1);
            CP_WAIT(1);
        } else {
            CP_WAIT(0);
        }
        __syncthreads();
        const uint32_t base = sb + (ch & 1) * STAGE_B;
        const uint32_t bbase = base + 2 * A_TILE_B;

#pragma unroll
        for (int ks = 0; ks < 2; ks++) {
            uint32_t aH[2][4], b[8][2];
#pragma unroll
            for (int mt = 0; mt < 2; mt++) {
                uint32_t off = ((mBase + mt * 16 + a_row) * TS + ks * 16 + a_koff) * 2;
                ldsm_x4(base + off, aH[mt][0], aH[mt][1], aH[mt][2], aH[mt][3]);
            }
#pragma unroll
            for (int g = 0; g < 4; g++) {
                uint32_t off = ((g * 16 + b_nrow) * TS + ks * 16 + b_koff) * 2;
                ldsm_x4(bbase + off,
                        b[2 * g][0], b[2 * g][1], b[2 * g + 1][0], b[2 * g + 1][1]);
            }
#pragma unroll
            for (int mt = 0; mt < 2; mt++)
#pragma unroll
                for (int nt = 0; nt < 8; nt++) mma16816(c[mt][nt], aH[mt], b[nt]);
            if (nprod >= 2) {
                uint32_t aL[2][4];
#pragma unroll
                for (int mt = 0; mt < 2; mt++) {
                    uint32_t off = ((mBase + mt * 16 + a_row) * TS + ks * 16 + a_koff) * 2;
                    ldsm_x4(base + A_TILE_B + off,
                            aL[mt][0], aL[mt][1], aL[mt][2], aL[mt][3]);
                }
#pragma unroll
                for (int mt = 0; mt < 2; mt++)
#pragma unroll
                    for (int nt = 0; nt < 8; nt++) mma16816(c[mt][nt], aL[mt], b[nt]);
            }
            if (nprod == 3) {
#pragma unroll
                for (int g = 0; g < 4; g++) {
                    uint32_t off = ((g * 16 + b_nrow) * TS + ks * 16 + b_koff) * 2;
                    ldsm_x4(bbase + B_TILE_B + off,
                            b[2 * g][0], b[2 * g][1], b[2 * g + 1][0], b[2 * g + 1][1]);
                }
#pragma unroll
                for (int mt = 0; mt < 2; mt++)
#pragma unroll
                    for (int nt = 0; nt < 8; nt++) mma16816(c[mt][nt], aH[mt], b[nt]);
            }
        }
        __syncthreads();
    }

#pragma unroll
    for (int mt = 0; mt < 2; mt++) {
#pragma unroll
        for (int half = 0; half < 2; half++) {
            int row = bm + mBase + mt * 16 + (lane >> 2) + half * 8;
#pragma unroll
            for (int nt = 0; nt < 8; nt++) {
                int col = bn + nt * 8 + (lane & 3) * 2;
                float v0 = c[mt][nt][2 * half];
                float v1 = c[mt][nt][2 * half + 1];
                if (QKV) {
                    size_t off = (size_t)row * D_MODEL + col;
                    float h0 = f16_rt(v0), h1 = f16_rt(v1);
                    *(uint32_t*)(H + off) = pack_f16(h0, h1);
                    if (storeL)
                        *(uint32_t*)(L + off) = pack_f16(v0 - h0, v1 - h1);
                } else {
                    *(float2*)(C + (size_t)row * D_MODEL + col) = make_float2(v0, v1);
                }
            }
        }
    }
}

// ---------------------------------------------------------------------------
// Conversion kernels
// ---------------------------------------------------------------------------
__global__ __launch_bounds__(256) void split_fp32(const float* __restrict__ s,
                                                  __half* __restrict__ h,
                                                  __half* __restrict__ l) {
    int i = blockIdx.x * 256 + threadIdx.x;
    float4 v = ((const float4*)s)[i];
    float a[4] = {v.x, v.y, v.z, v.w};
    uint32_t hh[2], ll[2];
#pragma unroll
    for (int j = 0; j < 2; j++) {
        float h0 = f16_rt(a[2 * j]), h1 = f16_rt(a[2 * j + 1]);
        hh[j] = pack_f16(h0, h1);
        ll[j] = pack_f16(a[2 * j] - h0, a[2 * j + 1] - h1);
    }
    ((uint32_t*)h)[2 * i] = hh[0];
    ((uint32_t*)h)[2 * i + 1] = hh[1];
    ((uint32_t*)l)[2 * i] = ll[0];
    ((uint32_t*)l)[2 * i + 1] = ll[1];
}

__global__ __launch_bounds__(256) void transpose_split4(const float* __restrict__ w0,
                                                        const float* __restrict__ w1,
                                                        const float* __restrict__ w2,
                                                        const float* __restrict__ w3) {
    __shared__ float t[32][33];
    const int z = blockIdx.z;
    const float* W = z == 0 ? w0 : z == 1 ? w1 : z == 2 ? w2 : w3;
    __half* Th = g_wh + (size_t)z * D_MODEL * D_MODEL;
    __half* Tl = g_wl + (size_t)z * D_MODEL * D_MODEL;
    const bool needL = (z < 2);   // only Q/K projections use wl

    int x = blockIdx.x * 32 + threadIdx.x;
    int y0 = blockIdx.y * 32;
#pragma unroll
    for (int j = 0; j < 32; j += 8)
        t[threadIdx.y + j][threadIdx.x] = W[(size_t)(y0 + threadIdx.y + j) * D_MODEL + x];
    __syncthreads();
    int xo = blockIdx.y * 32 + threadIdx.x;
    int yo = blockIdx.x * 32;
#pragma unroll
    for (int j = 0; j < 32; j += 8) {
        float v = t[threadIdx.x][threadIdx.y + j];
        float hv = f16_rt(v);
        Th[(size_t)(yo + threadIdx.y + j) * D_MODEL + xo] = __float2half_rn(v);
        if (needL)
            Tl[(size_t)(yo + threadIdx.y + j) * D_MODEL + xo] = __float2half_rn(v - hv);
    }
}

// ---------------------------------------------------------------------------
// Tensor-core causal flash attention, split-fp16, Q-in-registers.
// 64x64 tiles, 128 threads, 2-stage cp.async KV prefetch (Kh, Kl, Vh).
// S = QhKh + QlKh + QhKl (3 prod). PV = Ph·Vh ONLY (1 prod — Pl dropped;
// error ~2^-12 matches the fp16-hi rounding already in V and the epilogue).
// Epilogue writes fp16-hi only. 3 CTAs/SM.
// ---------------------------------------------------------------------------
#define TS2 72
#define ATILE_B (64 * TS2 * 2)       // 9216 bytes per tile
#define KV_STAGE (3 * ATILE_B)       // 27648
#define ATTN_SMEM (2 * KV_STAGE)     // 55296

__global__ __launch_bounds__(128, 3) void attn_tc() {
    extern __shared__ __align__(16) char asmc[];
    const uint32_t sb = smem_u32(asmc);

    const int tid = threadIdx.x;
    const int lane = tid & 31;
    const int wq = tid >> 5;
    const int qb = gridDim.x - 1 - blockIdx.x;  // heavy blocks first
    const int bh = blockIdx.y;
    const int b = bh >> 4, h = bh & 15;

    const uint32_t a_off = ((wq * 16 + (lane & 15)) * TS2 + (lane >> 4) * 8) * 2;
    const uint32_t b_off = ((((lane >> 4) * 8) + (lane & 7)) * TS2 + ((lane >> 3) & 1) * 8) * 2;
    const uint32_t v_off = ((((lane >> 3) & 1) * 8 + (lane & 7)) * TS2 + (lane >> 4) * 8) * 2;

    // ---- stage Q through KV stage 0, hoist fragments to registers ----
    uint32_t qH[4][4], qL[4][4];
    {
        const size_t base = (size_t)(b * SEQ + qb * 64) * D_MODEL + h * 64;
#pragma unroll
        for (int it = 0; it < 4; it++) {
            int idx = tid + it * 128;
            int r = idx >> 3, c8 = (idx & 7) * 8;
            size_t g = base + (size_t)r * D_MODEL + c8;
            uint32_t so = (r * TS2 + c8) * 2;
            cp16(sb + so, g_qh + g);
            cp16(sb + ATILE_B + so, g_ql + g);
        }
        CP_COMMIT();
        CP_WAIT(0);
        __syncthreads();
#pragma unroll
        for (int ks = 0; ks < 4; ks++) {
            ldsm_x4(sb + a_off + ks * 32, qH[ks][0], qH[ks][1], qH[ks][2], qH[ks][3]);
            ldsm_x4(sb + ATILE_B + a_off + ks * 32, qL[ks][0], qL[ks][1], qL[ks][2], qL[ks][3]);
        }
        __syncthreads();  // all warps done reading Q before KV overwrites stage 0
    }

    auto issue_kv = [&](int kb, int stage) {
        const size_t base = (size_t)(b * SEQ + kb * 64) * D_MODEL + h * 64;
        const uint32_t kvb = sb + stage * KV_STAGE;
#pragma unroll
        for (int it = 0; it < 4; it++) {
            int idx = tid + it * 128;
            int r = idx >> 3, c8 = (idx & 7) * 8;
            size_t g = base + (size_t)r * D_MODEL + c8;
            uint32_t so = (r * TS2 + c8) * 2;
            cp16(kvb + so, g_kh + g);
            cp16(kvb + ATILE_B + so, g_kl + g);
            cp16(kvb + 2 * ATILE_B + so, g_vh + g);
        }
        CP_COMMIT();
    };

    issue_kv(0, 0);

    float O[8][4];
#pragma unroll
    for (int nt = 0; nt < 8; nt++)
#pragma unroll
        for (int j = 0; j < 4; j++) O[nt][j] = 0.0f;
    float mrow[2] = {-1e30f, -1e30f};
    float lrow[2] = {0.0f, 0.0f};

    const float scale2 = 0.03125f * 1.44269504088896f;  // scale * log2(e)

    const int row0 = qb * 64 + wq * 16 + (lane >> 2);

    for (int kb = 0; kb <= qb; kb++) {
        CP_WAIT(0);
        __syncthreads();
        if (kb < qb) issue_kv(kb + 1, (kb + 1) & 1);  // overlaps with compute

        const uint32_t kvb = sb + (kb & 1) * KV_STAGE;
        const uint32_t SKH = kvb, SKL = kvb + ATILE_B, SVH = kvb + 2 * ATILE_B;

        // ---- S = Q @ K^T (3 products; Q from registers) ----
        float s[8][4];
#pragma unroll
        for (int nt = 0; nt < 8; nt++)
#pragma unroll
            for (int j = 0; j < 4; j++) s[nt][j] = 0.0f;

#pragma unroll
        for (int ks = 0; ks < 4; ks++) {
            uint32_t bk[8][2];
#pragma unroll
            for (int g = 0; g < 4; g++)
                ldsm_x4(SKH + b_off + g * 16 * TS2 * 2 + ks * 32,
                        bk[2 * g][0], bk[2 * g][1], bk[2 * g + 1][0], bk[2 * g + 1][1]);
#pragma unroll
            for (int nt = 0; nt < 8; nt++) mma16816(s[nt], qH[ks], bk[nt]);
#pragma unroll
            for (int nt = 0; nt < 8; nt++) mma16816(s[nt], qL[ks], bk[nt]);
#pragma unroll
            for (int g = 0; g < 4; g++)
                ldsm_x4(SKL + b_off + g * 16 * TS2 * 2 + ks * 32,
                        bk[2 * g][0], bk[2 * g][1], bk[2 * g + 1][0], bk[2 * g + 1][1]);
#pragma unroll
            for (int nt = 0; nt < 8; nt++) mma16816(s[nt], qH[ks], bk[nt]);
        }

        // ---- scale + mask + online softmax (base-2) ----
        const bool diag = (kb == qb);
#pragma unroll
        for (int i = 0; i < 2; i++) {
            const int rg = row0 + i * 8;
            float mx = -1e30f;
#pragma unroll
            for (int nt = 0; nt < 8; nt++) {
#pragma unroll
                for (int j = 0; j < 2; j++) {
                    float v = s[nt][2 * i + j] * scale2;
                    if (diag) {
                        int cg = kb * 64 + nt * 8 + (lane & 3) * 2 + j;
                        if (cg > rg) v = -1e30f;
                    }
                    s[nt][2 * i + j] = v;
                    mx = fmaxf(mx, v);
                }
            }
            mx = fmaxf(mx, __shfl_xor_sync(0xffffffffu, mx, 1));
            mx = fmaxf(mx, __shfl_xor_sync(0xffffffffu, mx, 2));
            float mn = fmaxf(mrow[i], mx);
            float alpha = ex2(mrow[i] - mn);
            mrow[i] = mn;
            float rs = 0.0f;
#pragma unroll
            for (int nt = 0; nt < 8; nt++) {
#pragma unroll
                for (int j = 0; j < 2; j++) {
                    float p = ex2(s[nt][2 * i + j] - mn);
                    s[nt][2 * i + j] = p;
                    rs += p;
                }
            }
            rs += __shfl_xor_sync(0xffffffffu, rs, 1);
            rs += __shfl_xor_sync(0xffffffffu, rs, 2);
            lrow[i] = lrow[i] * alpha + rs;
#pragma unroll
            for (int nt = 0; nt < 8; nt++) {
                O[nt][2 * i] *= alpha;
                O[nt][2 * i + 1] *= alpha;
            }
        }

        // ---- O += P @ V (1 product: Ph·Vh) ----
#pragma unroll
        for (int g = 0; g < 4; g++) {
            uint32_t pH[4];
#pragma unroll
            for (int q2 = 0; q2 < 2; q2++) {
#pragma unroll
                for (int half = 0; half < 2; half++) {
                    float v0 = s[2 * g + q2][2 * half];
                    float v1 = s[2 * g + q2][2 * half + 1];
                    pH[2 * q2 + half] = pack_f16(f16_rt(v0), f16_rt(v1));
                }
            }
            uint32_t bv[8][2];
#pragma unroll
            for (int gn = 0; gn < 4; gn++)
                ldsm_x4_t(SVH + v_off + (g * 16 * TS2 + gn * 16) * 2,
                          bv[2 * gn][0], bv[2 * gn][1], bv[2 * gn + 1][0], bv[2 * gn + 1][1]);
#pragma unroll
            for (int nt = 0; nt < 8; nt++) mma16816(O[nt], pH, bv[nt]);
        }
    }

    // ---- epilogue: fp16-hi only (out-proj is 1-product) ----
#pragma unroll
    for (int i = 0; i < 2; i++) {
        float inv = 1.0f / lrow[i];
        size_t row = (size_t)(b * SEQ) + row0 + i * 8;
#pragma unroll
        for (int nt = 0; nt < 8; nt++) {
            size_t off = row * D_MODEL + h * 64 + nt * 8 + (lane & 3) * 2;
            float v0 = O[nt][2 * i] * inv;
            float v1 = O[nt][2 * i + 1] * inv;
            *(uint32_t*)(g_ah + off) = pack_f16(f16_rt(v0), f16_rt(v1));
        }
    }
}

// ---------------------------------------------------------------------------
// kernel_launch: x, qw, kw, vw, ow (fp32)
// ---------------------------------------------------------------------------
extern "C" void kernel_launch(void* const* d_in, const int* in_sizes, int n_in,
                              void* d_out, int out_size) {
    const float* x = (const float*)d_in[0];
    float* out = (float*)d_out;

    __half *xh, *xl, *ah, *wh, *wl;
    cudaGetSymbolAddress((void**)&xh, g_xh);
    cudaGetSymbolAddress((void**)&xl, g_xl);
    cudaGetSymbolAddress((void**)&ah, g_ah);
    cudaGetSymbolAddress((void**)&wh, g_wh);
    cudaGetSymbolAddress((void**)&wl, g_wl);

    cudaFuncSetAttribute(gemm_pipe<1>, cudaFuncAttributeMaxDynamicSharedMemorySize,
                         GEMM_SMEM);
    cudaFuncSetAttribute(gemm_pipe<0>, cudaFuncAttributeMaxDynamicSharedMemorySize,
                         GEMM_SMEM);
    cudaFuncSetAttribute(attn_tc, cudaFuncAttributeMaxDynamicSharedMemorySize,
                         ATTN_SMEM);

    // 1. split x into fp16 hi/lo
    split_fp32<<<(ROWS * D_MODEL / 4) / 256, 256>>>(x, xh, xl);
    // 2. transpose+split all 4 weights (one launch; wl only for Q/K)
    transpose_split4<<<dim3(32, 32, 4), dim3(32, 8)>>>(
        (const float*)d_in[1], (const float*)d_in[2],
        (const float*)d_in[3], (const float*)d_in[4]);

    // 3. fused Q/K/V projections (Q,K 3-product; V 1-product)
    gemm_pipe<1><<<dim3(D_MODEL / 64, ROWS / 128, 3), 128, GEMM_SMEM>>>(
        nullptr, nullptr, nullptr, nullptr, nullptr, nullptr, nullptr);

    // 4. tensor-core attention (PV 1-product)
    attn_tc<<<dim3(SEQ / 64, BATCH * N_HEADS), 128, ATTN_SMEM>>>();

    // 5. output projection (1-product: ah @ owh, fp32 epilogue to d_out)
    gemm_pipe<0><<<dim3(D_MODEL / 64, ROWS / 128, 1), 128, GEMM_SMEM>>>(
        ah, nullptr, wh + 3u * D_MODEL * D_MODEL, nullptr, out, nullptr, nullptr);
}